// round 1
// baseline (speedup 1.0000x reference)
#include <cuda_runtime.h>
#include <cuda_bf16.h>
#include <math.h>

// Problem constants
#define S      2048
#define Hdim   2048
#define KVdim  512
#define NH     32
#define NKV    8
#define HD     64
#define SCALE  0.125f   // 1/sqrt(64)

// ---------------------------------------------------------------------------
// Scratch (device globals; no allocation allowed)
// ---------------------------------------------------------------------------
__device__ float g_q[S * Hdim];     // [s][head*64+d], RoPE'd in place
__device__ float g_k[S * KVdim];    // [s][kvhead*64+d]
__device__ float g_v[S * KVdim];
__device__ float g_attn[S * Hdim];  // attention output, [s][head*64+d]

// ---------------------------------------------------------------------------
// Tiled fp32 GEMM:  C[M,N] = A[M,K] * B[N,K]^T   (both operands K-major)
// BM=BN=64, BK=16, 256 threads, 4x4 microtile per thread.
// All M,N,K here are multiples of the tile sizes -> no bounds checks.
// ---------------------------------------------------------------------------
#define BM 64
#define BN 64
#define BKK 16

__global__ __launch_bounds__(256) void gemm_nt_kernel(
    const float* __restrict__ A, const float* __restrict__ B,
    float* __restrict__ C, int M, int N, int K)
{
    __shared__ float As[BKK][BM];
    __shared__ float Bs[BKK][BN];

    int tid = threadIdx.x;
    int bm = blockIdx.y * BM;
    int bn = blockIdx.x * BN;
    int ty = tid >> 4;        // 0..15 -> m group
    int tx = tid & 15;        // 0..15 -> n group

    int lrow = tid >> 2;          // 0..63
    int lk4  = (tid & 3) * 4;     // 0,4,8,12

    float acc[4][4];
#pragma unroll
    for (int i = 0; i < 4; i++)
#pragma unroll
        for (int j = 0; j < 4; j++) acc[i][j] = 0.f;

    for (int k0 = 0; k0 < K; k0 += BKK) {
        float4 a = *(const float4*)(A + (size_t)(bm + lrow) * K + k0 + lk4);
        float4 b = *(const float4*)(B + (size_t)(bn + lrow) * K + k0 + lk4);
        As[lk4 + 0][lrow] = a.x; As[lk4 + 1][lrow] = a.y;
        As[lk4 + 2][lrow] = a.z; As[lk4 + 3][lrow] = a.w;
        Bs[lk4 + 0][lrow] = b.x; Bs[lk4 + 1][lrow] = b.y;
        Bs[lk4 + 2][lrow] = b.z; Bs[lk4 + 3][lrow] = b.w;
        __syncthreads();

#pragma unroll
        for (int k = 0; k < BKK; k++) {
            float ra[4], rb[4];
#pragma unroll
            for (int i = 0; i < 4; i++) ra[i] = As[k][ty * 4 + i];
#pragma unroll
            for (int j = 0; j < 4; j++) rb[j] = Bs[k][tx * 4 + j];
#pragma unroll
            for (int i = 0; i < 4; i++)
#pragma unroll
                for (int j = 0; j < 4; j++)
                    acc[i][j] += ra[i] * rb[j];
        }
        __syncthreads();
    }

#pragma unroll
    for (int i = 0; i < 4; i++) {
        float* crow = C + (size_t)(bm + ty * 4 + i) * N + bn + tx * 4;
#pragma unroll
        for (int j = 0; j < 4; j++) crow[j] = acc[i][j];
    }
}

// ---------------------------------------------------------------------------
// RoPE over q and k in place.  One thread per (s, head-slot, i<32) pair.
// head-slot 0..31 -> q heads, 32..39 -> k heads.
// ---------------------------------------------------------------------------
__global__ void rope_kernel()
{
    int idx = blockIdx.x * blockDim.x + threadIdx.x;
    const int total = S * (NH + NKV) * 32;
    if (idx >= total) return;

    int i   = idx & 31;
    int r   = idx >> 5;
    int hs  = r % (NH + NKV);
    int s   = r / (NH + NKV);

    // inv_freq = 10000^(-i/32)
    float inv_freq = __powf(10000.0f, -(float)i / 32.0f);
    float angle = (float)s * inv_freq;
    float c, sn;
    sincosf(angle, &sn, &c);

    float* base;
    if (hs < NH) base = g_q + (size_t)s * Hdim + hs * HD;
    else         base = g_k + (size_t)s * KVdim + (hs - NH) * HD;

    float x1 = base[i];
    float x2 = base[i + 32];
    base[i]      = x1 * c - x2 * sn;
    base[i + 32] = x2 * c + x1 * sn;
}

// ---------------------------------------------------------------------------
// Flash-style causal attention.
// grid.x = S/8 (q row blocks), grid.y = NH.  256 threads = 8 warps.
// Warp w handles query row q0 + w.  64-key chunks staged in smem.
//   Ks stored [d][key]  -> score reads conflict-free
//   Vs stored [key][d]  -> PV reads conflict-free
// ---------------------------------------------------------------------------
__global__ __launch_bounds__(256) void flash_attn_kernel()
{
    __shared__ float Ks[64][64];   // [d][key]
    __shared__ float Vs[64][64];   // [key][d]
    __shared__ float Qs[8][64];

    int h   = blockIdx.y;
    int kvh = h >> 2;
    int q0  = blockIdx.x * 8;
    int tid = threadIdx.x;
    int w    = tid >> 5;
    int lane = tid & 31;
    int row  = q0 + w;

    // Load Q row for this warp, fold in softmax scale.
    {
        const float* qp = g_q + (size_t)row * Hdim + h * HD;
        Qs[w][lane]      = qp[lane] * SCALE;
        Qs[w][lane + 32] = qp[lane + 32] * SCALE;
    }

    float m = -1e30f, l = 0.f, o0 = 0.f, o1 = 0.f;
    int kend = q0 + 8;   // max key (exclusive) needed by any row in this block

    for (int kk = 0; kk < kend; kk += 64) {
        __syncthreads();
        // Stage K and V chunk (64 keys x 64 dims each)
        for (int e = tid; e < 4096; e += 256) {
            int key = e >> 6;
            int d   = e & 63;
            float kv = g_k[(size_t)(kk + key) * KVdim + kvh * HD + d];
            float vv = g_v[(size_t)(kk + key) * KVdim + kvh * HD + d];
            Ks[d][key] = kv;
            Vs[key][d] = vv;
        }
        __syncthreads();

        // Scores: lane handles keys kk+lane and kk+lane+32
        float s0 = 0.f, s1 = 0.f;
#pragma unroll 16
        for (int d = 0; d < 64; d++) {
            float qv = Qs[w][d];
            s0 += qv * Ks[d][lane];
            s1 += qv * Ks[d][lane + 32];
        }
        if (kk + lane      > row) s0 = -1e30f;
        if (kk + lane + 32 > row) s1 = -1e30f;

        // Online softmax
        float smax = fmaxf(s0, s1);
#pragma unroll
        for (int off = 16; off; off >>= 1)
            smax = fmaxf(smax, __shfl_xor_sync(0xFFFFFFFFu, smax, off));
        float mnew = fmaxf(m, smax);
        float corr = __expf(m - mnew);
        l *= corr; o0 *= corr; o1 *= corr;

        float p0 = __expf(s0 - mnew);
        float p1 = __expf(s1 - mnew);
        float ps = p0 + p1;
#pragma unroll
        for (int off = 16; off; off >>= 1)
            ps += __shfl_xor_sync(0xFFFFFFFFu, ps, off);
        l += ps;
        m = mnew;

        // o += P @ V  (broadcast p_j across lanes; lane owns dims lane, lane+32)
#pragma unroll
        for (int j = 0; j < 32; j++) {
            float pj0 = __shfl_sync(0xFFFFFFFFu, p0, j);
            float pj1 = __shfl_sync(0xFFFFFFFFu, p1, j);
            o0 += pj0 * Vs[j][lane]      + pj1 * Vs[j + 32][lane];
            o1 += pj0 * Vs[j][lane + 32] + pj1 * Vs[j + 32][lane + 32];
        }
    }

    float inv = 1.f / l;
    float* op = g_attn + (size_t)row * Hdim + h * HD;
    op[lane]      = o0 * inv;
    op[lane + 32] = o1 * inv;
}

// ---------------------------------------------------------------------------
// Launch
// ---------------------------------------------------------------------------
extern "C" void kernel_launch(void* const* d_in, const int* in_sizes, int n_in,
                              void* d_out, int out_size)
{
    const float* hs = (const float*)d_in[0];
    const float* Wq = (const float*)d_in[1];
    const float* Wk = (const float*)d_in[2];
    const float* Wv = (const float*)d_in[3];
    const float* Wo = (const float*)d_in[4];
    float* out = (float*)d_out;

    float *qp, *kp, *vp, *ap;
    cudaGetSymbolAddress((void**)&qp, g_q);
    cudaGetSymbolAddress((void**)&kp, g_k);
    cudaGetSymbolAddress((void**)&vp, g_v);
    cudaGetSymbolAddress((void**)&ap, g_attn);

    // QKV projections
    gemm_nt_kernel<<<dim3(Hdim / BN, S / BM), 256>>>(hs, Wq, qp, S, Hdim, Hdim);
    gemm_nt_kernel<<<dim3(KVdim / BN, S / BM), 256>>>(hs, Wk, kp, S, KVdim, Hdim);
    gemm_nt_kernel<<<dim3(KVdim / BN, S / BM), 256>>>(hs, Wv, vp, S, KVdim, Hdim);

    // RoPE on q and k
    {
        int total = S * (NH + NKV) * 32;
        rope_kernel<<<(total + 255) / 256, 256>>>();
    }

    // Causal attention
    flash_attn_kernel<<<dim3(S / 8, NH), 256>>>();

    // Output projection
    gemm_nt_kernel<<<dim3(Hdim / BN, S / BM), 256>>>(ap, Wo, out, S, Hdim, Hdim);
}

// round 2
// speedup vs baseline: 2.7813x; 2.7813x over previous
#include <cuda_runtime.h>
#include <cuda_bf16.h>
#include <math.h>

// Problem constants
#define S      2048
#define Hdim   2048
#define KVdim  512
#define NH     32
#define NKV    8
#define HD     64
#define SCALE  0.125f   // 1/sqrt(64)

// ---------------------------------------------------------------------------
// Scratch (device globals; no allocation allowed)
// ---------------------------------------------------------------------------
__device__ float g_q[S * Hdim];     // [s][head*64+d], RoPE'd in place
__device__ float g_k[S * KVdim];
__device__ float g_v[S * KVdim];
__device__ float g_attn[S * Hdim];

// ---------------------------------------------------------------------------
// tf32x3 split GEMM on tensor cores:  C[M,N] = A[M,K] * B[N,K]^T
// BM=BN=128, BK=32, 256 threads (8 warps: 4 in M x 2 in N, 32x64 per warp).
// A,B split into tf32 hi+lo during staging; C = AhBh + AhBl + AlBh (fp32 acc).
// Padded smem stride 36 floats -> fragment LDS conflict-free.
// ---------------------------------------------------------------------------
#define GBM 128
#define GBN 128
#define GBK 32
#define LDT 36

__device__ __forceinline__ unsigned f2tf(float x) {
    unsigned r;
    asm("cvt.rna.tf32.f32 %0, %1;" : "=r"(r) : "f"(x));
    return r;
}

__device__ __forceinline__ void mma_tf32(float d[4], const unsigned a[4], const unsigned b[2]) {
    asm volatile(
        "mma.sync.aligned.m16n8k8.row.col.f32.tf32.tf32.f32 "
        "{%0,%1,%2,%3}, {%4,%5,%6,%7}, {%8,%9}, {%0,%1,%2,%3};"
        : "+f"(d[0]), "+f"(d[1]), "+f"(d[2]), "+f"(d[3])
        : "r"(a[0]), "r"(a[1]), "r"(a[2]), "r"(a[3]), "r"(b[0]), "r"(b[1]));
}

__global__ __launch_bounds__(256) void gemm_tf32x3_nt(
    const float* __restrict__ A, const float* __restrict__ B,
    float* __restrict__ C, int M, int N, int K)
{
    extern __shared__ unsigned smu[];
    unsigned* Ah = smu;
    unsigned* Al = Ah + GBM * LDT;
    unsigned* Bh = Al + GBM * LDT;
    unsigned* Bl = Bh + GBM * LDT;

    int tid  = threadIdx.x;
    int wid  = tid >> 5, lane = tid & 31;
    int wm   = (wid & 3) * 32;   // warp m offset
    int wn   = (wid >> 2) * 64;  // warp n offset
    int bm   = blockIdx.y * GBM;
    int bn   = blockIdx.x * GBN;
    int g    = lane >> 2;        // group 0..7
    int tg   = lane & 3;         // 0..3

    int lrow = tid >> 3;         // 0..31 (staging row)
    int lc   = (tid & 7) * 4;    // 0..28 (staging k col)

    float acc[2][8][4];
#pragma unroll
    for (int i = 0; i < 2; i++)
#pragma unroll
        for (int j = 0; j < 8; j++)
#pragma unroll
            for (int c = 0; c < 4; c++) acc[i][j][c] = 0.f;

    for (int k0 = 0; k0 < K; k0 += GBK) {
        __syncthreads();
        // Stage + split A and B tiles
#pragma unroll
        for (int p = 0; p < 4; p++) {
            int row = lrow + p * 32;
            float4 va = *(const float4*)(A + (size_t)(bm + row) * K + k0 + lc);
            float4 vb = *(const float4*)(B + (size_t)(bn + row) * K + k0 + lc);
            float av[4] = {va.x, va.y, va.z, va.w};
            float bv[4] = {vb.x, vb.y, vb.z, vb.w};
#pragma unroll
            for (int c = 0; c < 4; c++) {
                unsigned h = f2tf(av[c]);
                Ah[row * LDT + lc + c] = h;
                Al[row * LDT + lc + c] = f2tf(av[c] - __uint_as_float(h));
                h = f2tf(bv[c]);
                Bh[row * LDT + lc + c] = h;
                Bl[row * LDT + lc + c] = f2tf(bv[c] - __uint_as_float(h));
            }
        }
        __syncthreads();

#pragma unroll
        for (int kt = 0; kt < 4; kt++) {
            int kk = kt * 8;
            unsigned ah[2][4], al[2][4], bh[8][2], bl[8][2];
#pragma unroll
            for (int tm = 0; tm < 2; tm++) {
                int r0 = (wm + tm * 16 + g) * LDT + kk + tg;
                int r8 = r0 + 8 * LDT;
                ah[tm][0] = Ah[r0]; ah[tm][1] = Ah[r8];
                ah[tm][2] = Ah[r0 + 4]; ah[tm][3] = Ah[r8 + 4];
                al[tm][0] = Al[r0]; al[tm][1] = Al[r8];
                al[tm][2] = Al[r0 + 4]; al[tm][3] = Al[r8 + 4];
            }
#pragma unroll
            for (int tn = 0; tn < 8; tn++) {
                int r = (wn + tn * 8 + g) * LDT + kk + tg;
                bh[tn][0] = Bh[r]; bh[tn][1] = Bh[r + 4];
                bl[tn][0] = Bl[r]; bl[tn][1] = Bl[r + 4];
            }
#pragma unroll
            for (int tm = 0; tm < 2; tm++)
#pragma unroll
                for (int tn = 0; tn < 8; tn++) {
                    mma_tf32(acc[tm][tn], ah[tm], bh[tn]);
                    mma_tf32(acc[tm][tn], al[tm], bh[tn]);
                    mma_tf32(acc[tm][tn], ah[tm], bl[tn]);
                }
        }
    }

    // Write back (c0,c1 contiguous -> float2; c2,c3 at row+8)
#pragma unroll
    for (int tm = 0; tm < 2; tm++)
#pragma unroll
        for (int tn = 0; tn < 8; tn++) {
            int row = bm + wm + tm * 16 + g;
            int col = bn + wn + tn * 8 + 2 * tg;
            float2* p0 = (float2*)(C + (size_t)row * N + col);
            float2* p1 = (float2*)(C + (size_t)(row + 8) * N + col);
            *p0 = make_float2(acc[tm][tn][0], acc[tm][tn][1]);
            *p1 = make_float2(acc[tm][tn][2], acc[tm][tn][3]);
        }
}

// ---------------------------------------------------------------------------
// RoPE over q and k in place.
// ---------------------------------------------------------------------------
__global__ void rope_kernel()
{
    int idx = blockIdx.x * blockDim.x + threadIdx.x;
    const int total = S * (NH + NKV) * 32;
    if (idx >= total) return;

    int i  = idx & 31;
    int r  = idx >> 5;
    int hs = r % (NH + NKV);
    int s  = r / (NH + NKV);

    float inv_freq = __powf(10000.0f, -(float)i / 32.0f);
    float angle = (float)s * inv_freq;
    float c, sn;
    sincosf(angle, &sn, &c);

    float* base;
    if (hs < NH) base = g_q + (size_t)s * Hdim + hs * HD;
    else         base = g_k + (size_t)s * KVdim + (hs - NH) * HD;

    float x1 = base[i];
    float x2 = base[i + 32];
    base[i]      = x1 * c - x2 * sn;
    base[i + 32] = x2 * c + x1 * sn;
}

// ---------------------------------------------------------------------------
// Flash-style causal attention, 32 q-rows per block (8 warps x 4 rows).
// 64-key chunks.  Ks[64][65] ([d][key], padded: conflict-free staging+reads),
// Vs[64][64] ([key][d]), Qs[32][64], Ps[32][64] (per-warp P rows via smem
// broadcast instead of shuffles).
// ---------------------------------------------------------------------------
__global__ __launch_bounds__(256) void flash_attn_kernel()
{
    extern __shared__ float sm[];
    float* Ks = sm;                 // 64*65
    float* Vs = Ks + 64 * 65;       // 64*64
    float* Qs = Vs + 64 * 64;       // 32*64
    float* Ps = Qs + 32 * 64;       // 32*64

    int h    = blockIdx.y;
    int kvh  = h >> 2;
    int q0   = blockIdx.x * 32;
    int tid  = threadIdx.x;
    int w    = tid >> 5;
    int lane = tid & 31;
    int row0 = q0 + w * 4;

    // Load Q rows for this block (scale folded in)
    for (int e = tid; e < 32 * 64; e += 256) {
        int r = e >> 6, d = e & 63;
        Qs[r * 64 + d] = g_q[(size_t)(q0 + r) * Hdim + h * HD + d] * SCALE;
    }

    float m[4], l[4], o0[4], o1[4];
#pragma unroll
    for (int r = 0; r < 4; r++) { m[r] = -1e30f; l[r] = 0.f; o0[r] = 0.f; o1[r] = 0.f; }

    int kend = q0 + 32;
    for (int kk = 0; kk < kend; kk += 64) {
        __syncthreads();
        for (int e = tid; e < 4096; e += 256) {
            int key = e >> 6, d = e & 63;
            Ks[d * 65 + key] = g_k[(size_t)(kk + key) * KVdim + kvh * HD + d];
            Vs[key * 64 + d] = g_v[(size_t)(kk + key) * KVdim + kvh * HD + d];
        }
        __syncthreads();

        // Scores: lane owns keys kk+lane, kk+lane+32; 4 rows per warp
        float s0[4] = {0.f, 0.f, 0.f, 0.f};
        float s1[4] = {0.f, 0.f, 0.f, 0.f};
#pragma unroll 8
        for (int d = 0; d < 64; d++) {
            float k0v = Ks[d * 65 + lane];
            float k1v = Ks[d * 65 + lane + 32];
#pragma unroll
            for (int r = 0; r < 4; r++) {
                float qv = Qs[(w * 4 + r) * 64 + d];
                s0[r] += qv * k0v;
                s1[r] += qv * k1v;
            }
        }

        // Online softmax per row; P -> smem
#pragma unroll
        for (int r = 0; r < 4; r++) {
            int row = row0 + r;
            float a = (kk + lane      > row) ? -1e30f : s0[r];
            float b = (kk + lane + 32 > row) ? -1e30f : s1[r];
            float smax = fmaxf(a, b);
#pragma unroll
            for (int off = 16; off; off >>= 1)
                smax = fmaxf(smax, __shfl_xor_sync(0xFFFFFFFFu, smax, off));
            float mnew = fmaxf(m[r], smax);
            float corr = __expf(m[r] - mnew);
            l[r] *= corr; o0[r] *= corr; o1[r] *= corr;
            float p0 = __expf(a - mnew);
            float p1 = __expf(b - mnew);
            float ps = p0 + p1;
#pragma unroll
            for (int off = 16; off; off >>= 1)
                ps += __shfl_xor_sync(0xFFFFFFFFu, ps, off);
            l[r] += ps;
            m[r] = mnew;
            Ps[(w * 4 + r) * 64 + lane]      = p0;
            Ps[(w * 4 + r) * 64 + lane + 32] = p1;
        }
        __syncwarp();

        // o += P @ V  (P broadcast from smem, V conflict-free)
#pragma unroll 4
        for (int j = 0; j < 64; j++) {
            float v0 = Vs[j * 64 + lane];
            float v1 = Vs[j * 64 + lane + 32];
#pragma unroll
            for (int r = 0; r < 4; r++) {
                float pj = Ps[(w * 4 + r) * 64 + j];
                o0[r] += pj * v0;
                o1[r] += pj * v1;
            }
        }
    }

#pragma unroll
    for (int r = 0; r < 4; r++) {
        float inv = 1.f / l[r];
        float* op = g_attn + (size_t)(row0 + r) * Hdim + h * HD;
        op[lane]      = o0[r] * inv;
        op[lane + 32] = o1[r] * inv;
    }
}

// ---------------------------------------------------------------------------
// Launch
// ---------------------------------------------------------------------------
extern "C" void kernel_launch(void* const* d_in, const int* in_sizes, int n_in,
                              void* d_out, int out_size)
{
    const float* hs = (const float*)d_in[0];
    const float* Wq = (const float*)d_in[1];
    const float* Wk = (const float*)d_in[2];
    const float* Wv = (const float*)d_in[3];
    const float* Wo = (const float*)d_in[4];
    float* out = (float*)d_out;

    float *qp, *kp, *vp, *ap;
    cudaGetSymbolAddress((void**)&qp, g_q);
    cudaGetSymbolAddress((void**)&kp, g_k);
    cudaGetSymbolAddress((void**)&vp, g_v);
    cudaGetSymbolAddress((void**)&ap, g_attn);

    const int gemm_smem = 4 * GBM * LDT * 4;          // 73728 B
    const int attn_smem = (64*65 + 64*64 + 32*64 + 32*64) * 4;  // 49408 B
    cudaFuncSetAttribute(gemm_tf32x3_nt,
                         cudaFuncAttributeMaxDynamicSharedMemorySize, gemm_smem);
    cudaFuncSetAttribute(flash_attn_kernel,
                         cudaFuncAttributeMaxDynamicSharedMemorySize, attn_smem);

    // QKV projections
    gemm_tf32x3_nt<<<dim3(Hdim / GBN, S / GBM), 256, gemm_smem>>>(hs, Wq, qp, S, Hdim, Hdim);
    gemm_tf32x3_nt<<<dim3(KVdim / GBN, S / GBM), 256, gemm_smem>>>(hs, Wk, kp, S, KVdim, Hdim);
    gemm_tf32x3_nt<<<dim3(KVdim / GBN, S / GBM), 256, gemm_smem>>>(hs, Wv, vp, S, KVdim, Hdim);

    // RoPE
    {
        int total = S * (NH + NKV) * 32;
        rope_kernel<<<(total + 255) / 256, 256>>>();
    }

    // Causal attention
    flash_attn_kernel<<<dim3(S / 32, NH), 256, attn_smem>>>();

    // Output projection
    gemm_tf32x3_nt<<<dim3(Hdim / GBN, S / GBM), 256, gemm_smem>>>(ap, Wo, out, S, Hdim, Hdim);
}

// round 3
// speedup vs baseline: 2.8591x; 1.0280x over previous
#include <cuda_runtime.h>
#include <cuda_bf16.h>
#include <math.h>

// Problem constants
#define S      2048
#define Hdim   2048
#define KVdim  512
#define NH     32
#define NKV    8
#define HD     64
#define SCALE  0.125f   // 1/sqrt(64)

// ---------------------------------------------------------------------------
// Scratch (device globals)
// ---------------------------------------------------------------------------
__device__ float g_q[S * Hdim];        // Q, RoPE'd in place
__device__ float g_kv[S * 1024];       // [s][0:512]=K, [s][512:1024]=V
__device__ float g_attn[S * Hdim];

// tf32 hi/lo pre-split operands
__device__ unsigned s_hs_h[S * Hdim],  s_hs_l[S * Hdim];
__device__ unsigned s_wq_h[Hdim * Hdim], s_wq_l[Hdim * Hdim];
__device__ unsigned s_wkv_h[1024 * Hdim], s_wkv_l[1024 * Hdim];  // rows 0-511 K, 512-1023 V
__device__ unsigned s_wo_h[Hdim * Hdim], s_wo_l[Hdim * Hdim];
__device__ unsigned s_at_h[S * Hdim],  s_at_l[S * Hdim];

__device__ __forceinline__ unsigned f2tf(float x) {
    unsigned r;
    asm("cvt.rna.tf32.f32 %0, %1;" : "=r"(r) : "f"(x));
    return r;
}

__device__ __forceinline__ void mma_tf32(float d[4], const unsigned a[4], const unsigned b[2]) {
    asm volatile(
        "mma.sync.aligned.m16n8k8.row.col.f32.tf32.tf32.f32 "
        "{%0,%1,%2,%3}, {%4,%5,%6,%7}, {%8,%9}, {%0,%1,%2,%3};"
        : "+f"(d[0]), "+f"(d[1]), "+f"(d[2]), "+f"(d[3])
        : "r"(a[0]), "r"(a[1]), "r"(a[2]), "r"(a[3]), "r"(b[0]), "r"(b[1]));
}

// ---------------------------------------------------------------------------
// Elementwise tf32 hi/lo split
// ---------------------------------------------------------------------------
__global__ void split_kernel(const float* __restrict__ src,
                             unsigned* __restrict__ h, unsigned* __restrict__ l, int n)
{
    int i = blockIdx.x * blockDim.x + threadIdx.x;
    if (i >= n) return;
    float x = src[i];
    unsigned hi = f2tf(x);
    h[i] = hi;
    l[i] = f2tf(x - __uint_as_float(hi));
}

// ---------------------------------------------------------------------------
// tf32x3 GEMM, pre-split operands:  C[M,N] = A[M,K] * B[N,K]^T
// BM=BN=128, BK=32, 256 threads (8 warps: 4 in M x 2 in N).
// ---------------------------------------------------------------------------
#define GBM 128
#define GBN 128
#define GBK 32
#define LDT 36

__global__ __launch_bounds__(256) void gemm_tf32x3_nt(
    const unsigned* __restrict__ Agh, const unsigned* __restrict__ Agl,
    const unsigned* __restrict__ Bgh, const unsigned* __restrict__ Bgl,
    float* __restrict__ C, int M, int N, int K)
{
    extern __shared__ unsigned smu[];
    unsigned* Ah = smu;
    unsigned* Al = Ah + GBM * LDT;
    unsigned* Bh = Al + GBM * LDT;
    unsigned* Bl = Bh + GBM * LDT;

    int tid  = threadIdx.x;
    int wid  = tid >> 5, lane = tid & 31;
    int wm   = (wid & 3) * 32;
    int wn   = (wid >> 2) * 64;
    int bm   = blockIdx.y * GBM;
    int bn   = blockIdx.x * GBN;
    int g    = lane >> 2;
    int tg   = lane & 3;

    int lrow = tid >> 3;         // 0..31
    int lc   = (tid & 7) * 4;    // 0..28

    float acc[2][8][4];
#pragma unroll
    for (int i = 0; i < 2; i++)
#pragma unroll
        for (int j = 0; j < 8; j++)
#pragma unroll
            for (int c = 0; c < 4; c++) acc[i][j][c] = 0.f;

    for (int k0 = 0; k0 < K; k0 += GBK) {
        __syncthreads();
#pragma unroll
        for (int p = 0; p < 4; p++) {
            int row = lrow + p * 32;
            size_t ga = (size_t)(bm + row) * K + k0 + lc;
            size_t gb = (size_t)(bn + row) * K + k0 + lc;
            *(uint4*)(Ah + row * LDT + lc) = *(const uint4*)(Agh + ga);
            *(uint4*)(Al + row * LDT + lc) = *(const uint4*)(Agl + ga);
            *(uint4*)(Bh + row * LDT + lc) = *(const uint4*)(Bgh + gb);
            *(uint4*)(Bl + row * LDT + lc) = *(const uint4*)(Bgl + gb);
        }
        __syncthreads();

#pragma unroll
        for (int kt = 0; kt < 4; kt++) {
            int kk = kt * 8;
            unsigned ah[2][4], al[2][4], bh[8][2], bl[8][2];
#pragma unroll
            for (int tm = 0; tm < 2; tm++) {
                int r0 = (wm + tm * 16 + g) * LDT + kk + tg;
                int r8 = r0 + 8 * LDT;
                ah[tm][0] = Ah[r0]; ah[tm][1] = Ah[r8];
                ah[tm][2] = Ah[r0 + 4]; ah[tm][3] = Ah[r8 + 4];
                al[tm][0] = Al[r0]; al[tm][1] = Al[r8];
                al[tm][2] = Al[r0 + 4]; al[tm][3] = Al[r8 + 4];
            }
#pragma unroll
            for (int tn = 0; tn < 8; tn++) {
                int r = (wn + tn * 8 + g) * LDT + kk + tg;
                bh[tn][0] = Bh[r]; bh[tn][1] = Bh[r + 4];
                bl[tn][0] = Bl[r]; bl[tn][1] = Bl[r + 4];
            }
#pragma unroll
            for (int tm = 0; tm < 2; tm++)
#pragma unroll
                for (int tn = 0; tn < 8; tn++) {
                    mma_tf32(acc[tm][tn], ah[tm], bh[tn]);
                    mma_tf32(acc[tm][tn], al[tm], bh[tn]);
                    mma_tf32(acc[tm][tn], ah[tm], bl[tn]);
                }
        }
    }

#pragma unroll
    for (int tm = 0; tm < 2; tm++)
#pragma unroll
        for (int tn = 0; tn < 8; tn++) {
            int row = bm + wm + tm * 16 + g;
            int col = bn + wn + tn * 8 + 2 * tg;
            *(float2*)(C + (size_t)row * N + col) =
                make_float2(acc[tm][tn][0], acc[tm][tn][1]);
            *(float2*)(C + (size_t)(row + 8) * N + col) =
                make_float2(acc[tm][tn][2], acc[tm][tn][3]);
        }
}

// ---------------------------------------------------------------------------
// RoPE over q (g_q) and k (g_kv cols 0-511) in place.
// ---------------------------------------------------------------------------
__global__ void rope_kernel()
{
    int idx = blockIdx.x * blockDim.x + threadIdx.x;
    const int total = S * (NH + NKV) * 32;
    if (idx >= total) return;

    int i  = idx & 31;
    int r  = idx >> 5;
    int hs = r % (NH + NKV);
    int s  = r / (NH + NKV);

    float inv_freq = __powf(10000.0f, -(float)i / 32.0f);
    float angle = (float)s * inv_freq;
    float c, sn;
    sincosf(angle, &sn, &c);

    float* base;
    if (hs < NH) base = g_q + (size_t)s * Hdim + hs * HD;
    else         base = g_kv + (size_t)s * 1024 + (hs - NH) * HD;

    float x1 = base[i];
    float x2 = base[i + 32];
    base[i]      = x1 * c - x2 * sn;
    base[i + 32] = x2 * c + x1 * sn;
}

// ---------------------------------------------------------------------------
// Tensor-core flash attention (causal).
// grid (S/64, NH), 128 threads (4 warps x 16 q-rows). 64-key chunks.
// tf32 mma for QK^T and P*V; fp32 online softmax in registers.
// Smem strides: Q/K/P stride 68 (banks 4g+tg bijective), V stride 72 (8tg+g).
// ---------------------------------------------------------------------------
__global__ __launch_bounds__(128) void flash_attn_tc()
{
    extern __shared__ unsigned smA[];
    unsigned* Qsm = smA;              // [64][68]
    unsigned* Ksm = Qsm + 64 * 68;    // [64][68]
    unsigned* Vsm = Ksm + 64 * 68;    // [64][72]
    unsigned* Psm = Vsm + 64 * 72;    // [4][16][68]

    int h   = blockIdx.y;
    int kvh = h >> 2;
    int q0  = blockIdx.x * 64;
    int tid = threadIdx.x;
    int w    = tid >> 5;
    int lane = tid & 31;
    int g    = lane >> 2;
    int tg   = lane & 3;

    // Stage Q (scale folded, tf32)
    for (int e = tid; e < 64 * 64; e += 128) {
        int r = e >> 6, d = e & 63;
        Qsm[r * 68 + d] = f2tf(g_q[(size_t)(q0 + r) * Hdim + h * HD + d] * SCALE);
    }
    __syncthreads();

    // Resident Q A-fragments (8 k-tiles)
    unsigned qa[8][4];
#pragma unroll
    for (int kt = 0; kt < 8; kt++) {
        int base = (w * 16 + g) * 68 + kt * 8 + tg;
        qa[kt][0] = Qsm[base];
        qa[kt][1] = Qsm[base + 8 * 68];
        qa[kt][2] = Qsm[base + 4];
        qa[kt][3] = Qsm[base + 8 * 68 + 4];
    }

    float oacc[8][4];
#pragma unroll
    for (int nt = 0; nt < 8; nt++)
#pragma unroll
        for (int c = 0; c < 4; c++) oacc[nt][c] = 0.f;

    float m0 = -1e30f, m1 = -1e30f, l0 = 0.f, l1 = 0.f;
    int row0 = q0 + w * 16 + g;
    int row1 = row0 + 8;
    unsigned* Pw = Psm + w * 16 * 68;

    for (int kk = 0; kk <= q0; kk += 64) {
        __syncthreads();
        for (int e = tid; e < 64 * 64; e += 128) {
            int r = e >> 6, d = e & 63;
            size_t gb = (size_t)(kk + r) * 1024 + kvh * HD + d;
            Ksm[r * 68 + d] = f2tf(g_kv[gb]);
            Vsm[r * 72 + d] = f2tf(g_kv[gb + 512]);
        }
        __syncthreads();

        // S = Q K^T
        float sacc[8][4];
#pragma unroll
        for (int nt = 0; nt < 8; nt++) {
#pragma unroll
            for (int c = 0; c < 4; c++) sacc[nt][c] = 0.f;
#pragma unroll
            for (int kt = 0; kt < 8; kt++) {
                int r = (nt * 8 + g) * 68 + kt * 8 + tg;
                unsigned b[2] = { Ksm[r], Ksm[r + 4] };
                mma_tf32(sacc[nt], qa[kt], b);
            }
        }

        // Causal mask (only the diagonal chunk can violate)
        if (kk == q0) {
#pragma unroll
            for (int nt = 0; nt < 8; nt++) {
                int col = kk + nt * 8 + 2 * tg;
                if (col     > row0) sacc[nt][0] = -1e30f;
                if (col + 1 > row0) sacc[nt][1] = -1e30f;
                if (col     > row1) sacc[nt][2] = -1e30f;
                if (col + 1 > row1) sacc[nt][3] = -1e30f;
            }
        }

        // Online softmax
        float mc0 = -1e30f, mc1 = -1e30f;
#pragma unroll
        for (int nt = 0; nt < 8; nt++) {
            mc0 = fmaxf(mc0, fmaxf(sacc[nt][0], sacc[nt][1]));
            mc1 = fmaxf(mc1, fmaxf(sacc[nt][2], sacc[nt][3]));
        }
        mc0 = fmaxf(mc0, __shfl_xor_sync(0xFFFFFFFFu, mc0, 1));
        mc0 = fmaxf(mc0, __shfl_xor_sync(0xFFFFFFFFu, mc0, 2));
        mc1 = fmaxf(mc1, __shfl_xor_sync(0xFFFFFFFFu, mc1, 1));
        mc1 = fmaxf(mc1, __shfl_xor_sync(0xFFFFFFFFu, mc1, 2));

        float mn0 = fmaxf(m0, mc0), mn1 = fmaxf(m1, mc1);
        float cr0 = __expf(m0 - mn0), cr1 = __expf(m1 - mn1);
        l0 *= cr0; l1 *= cr1;
#pragma unroll
        for (int nt = 0; nt < 8; nt++) {
            oacc[nt][0] *= cr0; oacc[nt][1] *= cr0;
            oacc[nt][2] *= cr1; oacc[nt][3] *= cr1;
        }
        m0 = mn0; m1 = mn1;

#pragma unroll
        for (int nt = 0; nt < 8; nt++) {
            float p0 = __expf(sacc[nt][0] - mn0);
            float p1 = __expf(sacc[nt][1] - mn0);
            float p2 = __expf(sacc[nt][2] - mn1);
            float p3 = __expf(sacc[nt][3] - mn1);
            l0 += p0 + p1;
            l1 += p2 + p3;
            int pb = g * 68 + nt * 8 + 2 * tg;
            *(uint2*)(Pw + pb)            = make_uint2(f2tf(p0), f2tf(p1));
            *(uint2*)(Pw + pb + 8 * 68)   = make_uint2(f2tf(p2), f2tf(p3));
        }
        __syncwarp();

        // O += P V
#pragma unroll
        for (int kt = 0; kt < 8; kt++) {
            unsigned pa[4];
            int pb = g * 68 + kt * 8 + tg;
            pa[0] = Pw[pb];
            pa[1] = Pw[pb + 8 * 68];
            pa[2] = Pw[pb + 4];
            pa[3] = Pw[pb + 8 * 68 + 4];
#pragma unroll
            for (int nt = 0; nt < 8; nt++) {
                int r = (kt * 8 + tg) * 72 + nt * 8 + g;
                unsigned b[2] = { Vsm[r], Vsm[r + 4 * 72] };
                mma_tf32(oacc[nt], pa, b);
            }
        }
    }

    // Finish l (quad holds disjoint column partials of each row)
    l0 += __shfl_xor_sync(0xFFFFFFFFu, l0, 1);
    l0 += __shfl_xor_sync(0xFFFFFFFFu, l0, 2);
    l1 += __shfl_xor_sync(0xFFFFFFFFu, l1, 1);
    l1 += __shfl_xor_sync(0xFFFFFFFFu, l1, 2);
    float inv0 = 1.f / l0, inv1 = 1.f / l1;

#pragma unroll
    for (int nt = 0; nt < 8; nt++) {
        int col = h * HD + nt * 8 + 2 * tg;
        *(float2*)(g_attn + (size_t)row0 * Hdim + col) =
            make_float2(oacc[nt][0] * inv0, oacc[nt][1] * inv0);
        *(float2*)(g_attn + (size_t)row1 * Hdim + col) =
            make_float2(oacc[nt][2] * inv1, oacc[nt][3] * inv1);
    }
}

// ---------------------------------------------------------------------------
// Launch
// ---------------------------------------------------------------------------
extern "C" void kernel_launch(void* const* d_in, const int* in_sizes, int n_in,
                              void* d_out, int out_size)
{
    const float* hs = (const float*)d_in[0];
    const float* Wq = (const float*)d_in[1];
    const float* Wk = (const float*)d_in[2];
    const float* Wv = (const float*)d_in[3];
    const float* Wo = (const float*)d_in[4];
    float* out = (float*)d_out;

    float *qp, *kvp, *ap;
    unsigned *hsh, *hsl, *wqh, *wql, *wkvh, *wkvl, *woh, *wol, *ath, *atl;
    cudaGetSymbolAddress((void**)&qp,  g_q);
    cudaGetSymbolAddress((void**)&kvp, g_kv);
    cudaGetSymbolAddress((void**)&ap,  g_attn);
    cudaGetSymbolAddress((void**)&hsh, s_hs_h);  cudaGetSymbolAddress((void**)&hsl, s_hs_l);
    cudaGetSymbolAddress((void**)&wqh, s_wq_h);  cudaGetSymbolAddress((void**)&wql, s_wq_l);
    cudaGetSymbolAddress((void**)&wkvh, s_wkv_h); cudaGetSymbolAddress((void**)&wkvl, s_wkv_l);
    cudaGetSymbolAddress((void**)&woh, s_wo_h);  cudaGetSymbolAddress((void**)&wol, s_wo_l);
    cudaGetSymbolAddress((void**)&ath, s_at_h);  cudaGetSymbolAddress((void**)&atl, s_at_l);

    const int gemm_smem = 4 * GBM * LDT * 4;
    const int attn_smem = (64 * 68 + 64 * 68 + 64 * 72 + 4 * 16 * 68) * 4;
    cudaFuncSetAttribute(gemm_tf32x3_nt,
                         cudaFuncAttributeMaxDynamicSharedMemorySize, gemm_smem);
    cudaFuncSetAttribute(flash_attn_tc,
                         cudaFuncAttributeMaxDynamicSharedMemorySize, attn_smem);

    // Pre-split inputs to tf32 hi/lo
    const int ST = 256;
    split_kernel<<<(S * Hdim + ST - 1) / ST, ST>>>(hs, hsh, hsl, S * Hdim);
    split_kernel<<<(Hdim * Hdim + ST - 1) / ST, ST>>>(Wq, wqh, wql, Hdim * Hdim);
    split_kernel<<<(KVdim * Hdim + ST - 1) / ST, ST>>>(Wk, wkvh, wkvl, KVdim * Hdim);
    split_kernel<<<(KVdim * Hdim + ST - 1) / ST, ST>>>(Wv, wkvh + (size_t)KVdim * Hdim,
                                                        wkvl + (size_t)KVdim * Hdim, KVdim * Hdim);
    split_kernel<<<(Hdim * Hdim + ST - 1) / ST, ST>>>(Wo, woh, wol, Hdim * Hdim);

    // Projections
    gemm_tf32x3_nt<<<dim3(Hdim / GBN, S / GBM), 256, gemm_smem>>>(
        hsh, hsl, wqh, wql, qp, S, Hdim, Hdim);
    gemm_tf32x3_nt<<<dim3(1024 / GBN, S / GBM), 256, gemm_smem>>>(
        hsh, hsl, wkvh, wkvl, kvp, S, 1024, Hdim);

    // RoPE
    {
        int total = S * (NH + NKV) * 32;
        rope_kernel<<<(total + 255) / 256, 256>>>();
    }

    // Attention
    flash_attn_tc<<<dim3(S / 64, NH), 128, attn_smem>>>();

    // Split attention output, then output projection
    split_kernel<<<(S * Hdim + ST - 1) / ST, ST>>>(ap, ath, atl, S * Hdim);
    gemm_tf32x3_nt<<<dim3(Hdim / GBN, S / GBM), 256, gemm_smem>>>(
        ath, atl, woh, wol, out, S, Hdim, Hdim);
}

// round 4
// speedup vs baseline: 6.4582x; 2.2588x over previous
#include <cuda_runtime.h>
#include <cuda_bf16.h>
#include <math.h>

// Problem constants
#define S      2048
#define Hdim   2048
#define KVdim  512
#define NH     32
#define NKV    8
#define HD     64
#define SCALE  0.125f

// ---------------------------------------------------------------------------
// Scratch (device globals)
// ---------------------------------------------------------------------------
__device__ float g_q[S * Hdim];        // Q fp32, RoPE'd in place
__device__ float g_kv[S * 1024];       // [s][0:512]=K, [s][512:1024]=V

// bf16 hi/lo pre-split operands
__device__ __nv_bfloat16 s_hs_h[S * Hdim],    s_hs_l[S * Hdim];
__device__ __nv_bfloat16 s_wq_h[Hdim * Hdim], s_wq_l[Hdim * Hdim];
__device__ __nv_bfloat16 s_wkv_h[1024 * Hdim], s_wkv_l[1024 * Hdim];
__device__ __nv_bfloat16 s_wo_h[Hdim * Hdim], s_wo_l[Hdim * Hdim];
__device__ __nv_bfloat16 s_at_h[S * Hdim],    s_at_l[S * Hdim];

__device__ __forceinline__ unsigned f2tf(float x) {
    unsigned r;
    asm("cvt.rna.tf32.f32 %0, %1;" : "=r"(r) : "f"(x));
    return r;
}

__device__ __forceinline__ void mma_tf32(float d[4], const unsigned a[4], const unsigned b[2]) {
    asm volatile(
        "mma.sync.aligned.m16n8k8.row.col.f32.tf32.tf32.f32 "
        "{%0,%1,%2,%3}, {%4,%5,%6,%7}, {%8,%9}, {%0,%1,%2,%3};"
        : "+f"(d[0]), "+f"(d[1]), "+f"(d[2]), "+f"(d[3])
        : "r"(a[0]), "r"(a[1]), "r"(a[2]), "r"(a[3]), "r"(b[0]), "r"(b[1]));
}

__device__ __forceinline__ void mma_bf16(float d[4], const unsigned a[4],
                                         unsigned b0, unsigned b1) {
    asm volatile(
        "mma.sync.aligned.m16n8k16.row.col.f32.bf16.bf16.f32 "
        "{%0,%1,%2,%3}, {%4,%5,%6,%7}, {%8,%9}, {%0,%1,%2,%3};"
        : "+f"(d[0]), "+f"(d[1]), "+f"(d[2]), "+f"(d[3])
        : "r"(a[0]), "r"(a[1]), "r"(a[2]), "r"(a[3]), "r"(b0), "r"(b1));
}

__device__ __forceinline__ unsigned bf2u(__nv_bfloat162 v) {
    return *(unsigned*)&v;
}

// ---------------------------------------------------------------------------
// Vectorized bf16 hi/lo split: 4 elems/thread
// ---------------------------------------------------------------------------
__global__ void split_bf16(const float4* __restrict__ src,
                           uint2* __restrict__ h, uint2* __restrict__ l, int n4)
{
    int i = blockIdx.x * blockDim.x + threadIdx.x;
    if (i >= n4) return;
    float4 v = src[i];
    __nv_bfloat162 h0 = __floats2bfloat162_rn(v.x, v.y);
    __nv_bfloat162 h1 = __floats2bfloat162_rn(v.z, v.w);
    __nv_bfloat162 l0 = __floats2bfloat162_rn(v.x - __bfloat162float(h0.x),
                                              v.y - __bfloat162float(h0.y));
    __nv_bfloat162 l1 = __floats2bfloat162_rn(v.z - __bfloat162float(h1.x),
                                              v.w - __bfloat162float(h1.y));
    h[i] = make_uint2(bf2u(h0), bf2u(h1));
    l[i] = make_uint2(bf2u(l0), bf2u(l1));
}

// ---------------------------------------------------------------------------
// bf16x3 GEMM, cp.async double-buffered:  C[M,N] = A[M,K] * B[N,K]^T
// BM=BN=128, BK=32, 256 threads (8 warps: 4 in M x 2 in N).
// Smem rows: 32 bf16 data padded to 20 u32 (fragment banks (20g+tg)%32 bijective).
// ---------------------------------------------------------------------------
#define ROWU 20
#define ARRU (128 * ROWU)
#define STGU (4 * ARRU)

__global__ __launch_bounds__(256) void gemm_bf16x3_nt(
    const __nv_bfloat16* __restrict__ Agh, const __nv_bfloat16* __restrict__ Agl,
    const __nv_bfloat16* __restrict__ Bgh, const __nv_bfloat16* __restrict__ Bgl,
    float* __restrict__ C, int M, int N, int K)
{
    extern __shared__ unsigned sm[];

    int tid = threadIdx.x, wid = tid >> 5, lane = tid & 31;
    int wm = (wid & 3) * 32, wn = (wid >> 2) * 64;
    int bm = blockIdx.y * 128, bn = blockIdx.x * 128;
    int g = lane >> 2, tg = lane & 3;
    int lr = tid >> 2, lch = tid & 3;

    unsigned smem_base = (unsigned)__cvta_generic_to_shared(sm);

    float acc[2][8][4];
#pragma unroll
    for (int i = 0; i < 2; i++)
#pragma unroll
        for (int j = 0; j < 8; j++)
#pragma unroll
            for (int c = 0; c < 4; c++) acc[i][j][c] = 0.f;

    auto issue = [&](int s, int k0) {
#pragma unroll
        for (int p = 0; p < 2; p++) {
            int row = lr + p * 64;
            unsigned soff = smem_base + (unsigned)(s * STGU + row * ROWU + lch * 4) * 4;
            const __nv_bfloat16* ga = Agh + (size_t)(bm + row) * K + k0 + lch * 8;
            asm volatile("cp.async.cg.shared.global [%0], [%1], 16;"
                         :: "r"(soff), "l"(ga));
            ga = Agl + (size_t)(bm + row) * K + k0 + lch * 8;
            asm volatile("cp.async.cg.shared.global [%0], [%1], 16;"
                         :: "r"(soff + ARRU * 4), "l"(ga));
            const __nv_bfloat16* gb = Bgh + (size_t)(bn + row) * K + k0 + lch * 8;
            asm volatile("cp.async.cg.shared.global [%0], [%1], 16;"
                         :: "r"(soff + 2 * ARRU * 4), "l"(gb));
            gb = Bgl + (size_t)(bn + row) * K + k0 + lch * 8;
            asm volatile("cp.async.cg.shared.global [%0], [%1], 16;"
                         :: "r"(soff + 3 * ARRU * 4), "l"(gb));
        }
    };

    int nk = K / 32;
    issue(0, 0);
    asm volatile("cp.async.commit_group;");

    for (int it = 0; it < nk; it++) {
        if (it + 1 < nk) {
            issue((it + 1) & 1, (it + 1) * 32);
            asm volatile("cp.async.commit_group;");
            asm volatile("cp.async.wait_group 1;");
        } else {
            asm volatile("cp.async.wait_group 0;");
        }
        __syncthreads();

        const unsigned* Ah_s = sm + (it & 1) * STGU;
        const unsigned* Al_s = Ah_s + ARRU;
        const unsigned* Bh_s = Ah_s + 2 * ARRU;
        const unsigned* Bl_s = Ah_s + 3 * ARRU;

#pragma unroll
        for (int ks = 0; ks < 2; ks++) {
            unsigned ah[2][4], al[2][4];
#pragma unroll
            for (int tm = 0; tm < 2; tm++) {
                int i0 = (wm + tm * 16 + g) * ROWU + ks * 8 + tg;
                ah[tm][0] = Ah_s[i0];             ah[tm][1] = Ah_s[i0 + 8 * ROWU];
                ah[tm][2] = Ah_s[i0 + 4];         ah[tm][3] = Ah_s[i0 + 8 * ROWU + 4];
                al[tm][0] = Al_s[i0];             al[tm][1] = Al_s[i0 + 8 * ROWU];
                al[tm][2] = Al_s[i0 + 4];         al[tm][3] = Al_s[i0 + 8 * ROWU + 4];
            }
#pragma unroll
            for (int nt = 0; nt < 8; nt++) {
                int ib = (wn + nt * 8 + g) * ROWU + ks * 8 + tg;
                unsigned bh0 = Bh_s[ib], bh1 = Bh_s[ib + 4];
                unsigned bl0 = Bl_s[ib], bl1 = Bl_s[ib + 4];
#pragma unroll
                for (int tm = 0; tm < 2; tm++) {
                    mma_bf16(acc[tm][nt], ah[tm], bh0, bh1);
                    mma_bf16(acc[tm][nt], al[tm], bh0, bh1);
                    mma_bf16(acc[tm][nt], ah[tm], bl0, bl1);
                }
            }
        }
        __syncthreads();
    }

#pragma unroll
    for (int tm = 0; tm < 2; tm++)
#pragma unroll
        for (int nt = 0; nt < 8; nt++) {
            int row = bm + wm + tm * 16 + g;
            int col = bn + wn + nt * 8 + 2 * tg;
            *(float2*)(C + (size_t)row * N + col) =
                make_float2(acc[tm][nt][0], acc[tm][nt][1]);
            *(float2*)(C + (size_t)(row + 8) * N + col) =
                make_float2(acc[tm][nt][2], acc[tm][nt][3]);
        }
}

// ---------------------------------------------------------------------------
// RoPE over q (g_q) and k (g_kv cols 0-511) in place.
// ---------------------------------------------------------------------------
__global__ void rope_kernel()
{
    int idx = blockIdx.x * blockDim.x + threadIdx.x;
    const int total = S * (NH + NKV) * 32;
    if (idx >= total) return;

    int i  = idx & 31;
    int r  = idx >> 5;
    int hs = r % (NH + NKV);
    int s  = r / (NH + NKV);

    float inv_freq = __powf(10000.0f, -(float)i / 32.0f);
    float angle = (float)s * inv_freq;
    float c, sn;
    sincosf(angle, &sn, &c);

    float* base;
    if (hs < NH) base = g_q + (size_t)s * Hdim + hs * HD;
    else         base = g_kv + (size_t)s * 1024 + (hs - NH) * HD;

    float x1 = base[i];
    float x2 = base[i + 32];
    base[i]      = x1 * c - x2 * sn;
    base[i + 32] = x2 * c + x1 * sn;
}

// ---------------------------------------------------------------------------
// Tensor-core flash attention (causal), tf32 mma, bf16-split fused epilogue.
// grid (S/64, NH), 128 threads (4 warps x 16 q-rows). 64-key chunks.
// ---------------------------------------------------------------------------
__global__ __launch_bounds__(128) void flash_attn_tc()
{
    extern __shared__ unsigned smA[];
    unsigned* Qsm = smA;              // [64][68]
    unsigned* Ksm = Qsm + 64 * 68;    // [64][68]
    unsigned* Vsm = Ksm + 64 * 68;    // [64][72]
    unsigned* Psm = Vsm + 64 * 72;    // [4][16][68]

    int h   = blockIdx.y;
    int kvh = h >> 2;
    int q0  = blockIdx.x * 64;
    int tid = threadIdx.x;
    int w    = tid >> 5;
    int lane = tid & 31;
    int g    = lane >> 2;
    int tg   = lane & 3;

    for (int e = tid; e < 64 * 64; e += 128) {
        int r = e >> 6, d = e & 63;
        Qsm[r * 68 + d] = f2tf(g_q[(size_t)(q0 + r) * Hdim + h * HD + d] * SCALE);
    }
    __syncthreads();

    unsigned qa[8][4];
#pragma unroll
    for (int kt = 0; kt < 8; kt++) {
        int base = (w * 16 + g) * 68 + kt * 8 + tg;
        qa[kt][0] = Qsm[base];
        qa[kt][1] = Qsm[base + 8 * 68];
        qa[kt][2] = Qsm[base + 4];
        qa[kt][3] = Qsm[base + 8 * 68 + 4];
    }

    float oacc[8][4];
#pragma unroll
    for (int nt = 0; nt < 8; nt++)
#pragma unroll
        for (int c = 0; c < 4; c++) oacc[nt][c] = 0.f;

    float m0 = -1e30f, m1 = -1e30f, l0 = 0.f, l1 = 0.f;
    int row0 = q0 + w * 16 + g;
    int row1 = row0 + 8;
    unsigned* Pw = Psm + w * 16 * 68;

    for (int kk = 0; kk <= q0; kk += 64) {
        __syncthreads();
        for (int e = tid; e < 64 * 64; e += 128) {
            int r = e >> 6, d = e & 63;
            size_t gb = (size_t)(kk + r) * 1024 + kvh * HD + d;
            Ksm[r * 68 + d] = f2tf(g_kv[gb]);
            Vsm[r * 72 + d] = f2tf(g_kv[gb + 512]);
        }
        __syncthreads();

        float sacc[8][4];
#pragma unroll
        for (int nt = 0; nt < 8; nt++) {
#pragma unroll
            for (int c = 0; c < 4; c++) sacc[nt][c] = 0.f;
#pragma unroll
            for (int kt = 0; kt < 8; kt++) {
                int r = (nt * 8 + g) * 68 + kt * 8 + tg;
                unsigned b[2] = { Ksm[r], Ksm[r + 4] };
                mma_tf32(sacc[nt], qa[kt], b);
            }
        }

        if (kk == q0) {
#pragma unroll
            for (int nt = 0; nt < 8; nt++) {
                int col = kk + nt * 8 + 2 * tg;
                if (col     > row0) sacc[nt][0] = -1e30f;
                if (col + 1 > row0) sacc[nt][1] = -1e30f;
                if (col     > row1) sacc[nt][2] = -1e30f;
                if (col + 1 > row1) sacc[nt][3] = -1e30f;
            }
        }

        float mc0 = -1e30f, mc1 = -1e30f;
#pragma unroll
        for (int nt = 0; nt < 8; nt++) {
            mc0 = fmaxf(mc0, fmaxf(sacc[nt][0], sacc[nt][1]));
            mc1 = fmaxf(mc1, fmaxf(sacc[nt][2], sacc[nt][3]));
        }
        mc0 = fmaxf(mc0, __shfl_xor_sync(0xFFFFFFFFu, mc0, 1));
        mc0 = fmaxf(mc0, __shfl_xor_sync(0xFFFFFFFFu, mc0, 2));
        mc1 = fmaxf(mc1, __shfl_xor_sync(0xFFFFFFFFu, mc1, 1));
        mc1 = fmaxf(mc1, __shfl_xor_sync(0xFFFFFFFFu, mc1, 2));

        float mn0 = fmaxf(m0, mc0), mn1 = fmaxf(m1, mc1);
        float cr0 = __expf(m0 - mn0), cr1 = __expf(m1 - mn1);
        l0 *= cr0; l1 *= cr1;
#pragma unroll
        for (int nt = 0; nt < 8; nt++) {
            oacc[nt][0] *= cr0; oacc[nt][1] *= cr0;
            oacc[nt][2] *= cr1; oacc[nt][3] *= cr1;
        }
        m0 = mn0; m1 = mn1;

#pragma unroll
        for (int nt = 0; nt < 8; nt++) {
            float p0 = __expf(sacc[nt][0] - mn0);
            float p1 = __expf(sacc[nt][1] - mn0);
            float p2 = __expf(sacc[nt][2] - mn1);
            float p3 = __expf(sacc[nt][3] - mn1);
            l0 += p0 + p1;
            l1 += p2 + p3;
            int pb = g * 68 + nt * 8 + 2 * tg;
            *(uint2*)(Pw + pb)          = make_uint2(f2tf(p0), f2tf(p1));
            *(uint2*)(Pw + pb + 8 * 68) = make_uint2(f2tf(p2), f2tf(p3));
        }
        __syncwarp();

#pragma unroll
        for (int kt = 0; kt < 8; kt++) {
            unsigned pa[4];
            int pb = g * 68 + kt * 8 + tg;
            pa[0] = Pw[pb];
            pa[1] = Pw[pb + 8 * 68];
            pa[2] = Pw[pb + 4];
            pa[3] = Pw[pb + 8 * 68 + 4];
#pragma unroll
            for (int nt = 0; nt < 8; nt++) {
                int r = (kt * 8 + tg) * 72 + nt * 8 + g;
                unsigned b[2] = { Vsm[r], Vsm[r + 4 * 72] };
                mma_tf32(oacc[nt], pa, b);
            }
        }
    }

    l0 += __shfl_xor_sync(0xFFFFFFFFu, l0, 1);
    l0 += __shfl_xor_sync(0xFFFFFFFFu, l0, 2);
    l1 += __shfl_xor_sync(0xFFFFFFFFu, l1, 1);
    l1 += __shfl_xor_sync(0xFFFFFFFFu, l1, 2);
    float inv0 = 1.f / l0, inv1 = 1.f / l1;

    // Fused bf16 hi/lo split epilogue
#pragma unroll
    for (int nt = 0; nt < 8; nt++) {
        int col = h * HD + nt * 8 + 2 * tg;
        {
            float a0 = oacc[nt][0] * inv0, a1 = oacc[nt][1] * inv0;
            __nv_bfloat162 hv = __floats2bfloat162_rn(a0, a1);
            __nv_bfloat162 lv = __floats2bfloat162_rn(a0 - __bfloat162float(hv.x),
                                                      a1 - __bfloat162float(hv.y));
            *(__nv_bfloat162*)(s_at_h + (size_t)row0 * Hdim + col) = hv;
            *(__nv_bfloat162*)(s_at_l + (size_t)row0 * Hdim + col) = lv;
        }
        {
            float a0 = oacc[nt][2] * inv1, a1 = oacc[nt][3] * inv1;
            __nv_bfloat162 hv = __floats2bfloat162_rn(a0, a1);
            __nv_bfloat162 lv = __floats2bfloat162_rn(a0 - __bfloat162float(hv.x),
                                                      a1 - __bfloat162float(hv.y));
            *(__nv_bfloat162*)(s_at_h + (size_t)row1 * Hdim + col) = hv;
            *(__nv_bfloat162*)(s_at_l + (size_t)row1 * Hdim + col) = lv;
        }
    }
}

// ---------------------------------------------------------------------------
// Launch
// ---------------------------------------------------------------------------
extern "C" void kernel_launch(void* const* d_in, const int* in_sizes, int n_in,
                              void* d_out, int out_size)
{
    const float* hs = (const float*)d_in[0];
    const float* Wq = (const float*)d_in[1];
    const float* Wk = (const float*)d_in[2];
    const float* Wv = (const float*)d_in[3];
    const float* Wo = (const float*)d_in[4];
    float* out = (float*)d_out;

    float *qp, *kvp;
    __nv_bfloat16 *hsh, *hsl, *wqh, *wql, *wkvh, *wkvl, *woh, *wol, *ath, *atl;
    cudaGetSymbolAddress((void**)&qp,  g_q);
    cudaGetSymbolAddress((void**)&kvp, g_kv);
    cudaGetSymbolAddress((void**)&hsh, s_hs_h);  cudaGetSymbolAddress((void**)&hsl, s_hs_l);
    cudaGetSymbolAddress((void**)&wqh, s_wq_h);  cudaGetSymbolAddress((void**)&wql, s_wq_l);
    cudaGetSymbolAddress((void**)&wkvh, s_wkv_h); cudaGetSymbolAddress((void**)&wkvl, s_wkv_l);
    cudaGetSymbolAddress((void**)&woh, s_wo_h);  cudaGetSymbolAddress((void**)&wol, s_wo_l);
    cudaGetSymbolAddress((void**)&ath, s_at_h);  cudaGetSymbolAddress((void**)&atl, s_at_l);

    const int gemm_smem = 2 * STGU * 4;   // 81920 B
    const int attn_smem = (64 * 68 + 64 * 68 + 64 * 72 + 4 * 16 * 68) * 4;
    cudaFuncSetAttribute(gemm_bf16x3_nt,
                         cudaFuncAttributeMaxDynamicSharedMemorySize, gemm_smem);
    cudaFuncSetAttribute(flash_attn_tc,
                         cudaFuncAttributeMaxDynamicSharedMemorySize, attn_smem);

    // Pre-split inputs to bf16 hi/lo (4 elems/thread)
    const int ST = 256;
    auto splitN = [&](const float* src, __nv_bfloat16* h, __nv_bfloat16* l, int n) {
        int n4 = n / 4;
        split_bf16<<<(n4 + ST - 1) / ST, ST>>>((const float4*)src, (uint2*)h, (uint2*)l, n4);
    };
    splitN(hs, hsh, hsl, S * Hdim);
    splitN(Wq, wqh, wql, Hdim * Hdim);
    splitN(Wk, wkvh, wkvl, KVdim * Hdim);
    splitN(Wv, wkvh + (size_t)KVdim * Hdim, wkvl + (size_t)KVdim * Hdim, KVdim * Hdim);
    splitN(Wo, woh, wol, Hdim * Hdim);

    // Projections
    gemm_bf16x3_nt<<<dim3(Hdim / 128, S / 128), 256, gemm_smem>>>(
        hsh, hsl, wqh, wql, qp, S, Hdim, Hdim);
    gemm_bf16x3_nt<<<dim3(1024 / 128, S / 128), 256, gemm_smem>>>(
        hsh, hsl, wkvh, wkvl, kvp, S, 1024, Hdim);

    // RoPE
    {
        int total = S * (NH + NKV) * 32;
        rope_kernel<<<(total + 255) / 256, 256>>>();
    }

    // Attention (writes bf16 hi/lo directly)
    flash_attn_tc<<<dim3(S / 64, NH), 128, attn_smem>>>();

    // Output projection
    gemm_bf16x3_nt<<<dim3(Hdim / 128, S / 128), 256, gemm_smem>>>(
        ath, atl, woh, wol, out, S, Hdim, Hdim);
}

// round 5
// speedup vs baseline: 7.0823x; 1.0966x over previous
#include <cuda_runtime.h>
#include <cuda_bf16.h>
#include <math.h>

// Problem constants
#define S      2048
#define Hdim   2048
#define KVdim  512
#define NH     32
#define NKV    8
#define HD     64
#define SCALE  0.125f

// ---------------------------------------------------------------------------
// Scratch (device globals)
// ---------------------------------------------------------------------------
__device__ float g_q[S * Hdim];        // Q fp32 from GEMM
__device__ float g_kv[S * 1024];       // [s][0:512]=K, [s][512:1024]=V

// tf32 head-major operands for attention (written by rope_conv)
__device__ unsigned g_qt[NH * S * HD];    // [h][s][d], scale folded
__device__ unsigned g_kt[NKV * S * HD];   // [kvh][s][d]
__device__ unsigned g_vt[NKV * S * HD];

// bf16 hi/lo pre-split operands for GEMMs
__device__ __nv_bfloat16 s_hs_h[S * Hdim],    s_hs_l[S * Hdim];
__device__ __nv_bfloat16 s_wq_h[Hdim * Hdim], s_wq_l[Hdim * Hdim];
__device__ __nv_bfloat16 s_wkv_h[1024 * Hdim], s_wkv_l[1024 * Hdim];
__device__ __nv_bfloat16 s_wo_h[Hdim * Hdim], s_wo_l[Hdim * Hdim];
__device__ __nv_bfloat16 s_at_h[S * Hdim],    s_at_l[S * Hdim];

__device__ __forceinline__ unsigned f2tf(float x) {
    unsigned r;
    asm("cvt.rna.tf32.f32 %0, %1;" : "=r"(r) : "f"(x));
    return r;
}

__device__ __forceinline__ void mma_tf32(float d[4], const unsigned a[4], const unsigned b[2]) {
    asm volatile(
        "mma.sync.aligned.m16n8k8.row.col.f32.tf32.tf32.f32 "
        "{%0,%1,%2,%3}, {%4,%5,%6,%7}, {%8,%9}, {%0,%1,%2,%3};"
        : "+f"(d[0]), "+f"(d[1]), "+f"(d[2]), "+f"(d[3])
        : "r"(a[0]), "r"(a[1]), "r"(a[2]), "r"(a[3]), "r"(b[0]), "r"(b[1]));
}

__device__ __forceinline__ void mma_bf16(float d[4], const unsigned a[4],
                                         unsigned b0, unsigned b1) {
    asm volatile(
        "mma.sync.aligned.m16n8k16.row.col.f32.bf16.bf16.f32 "
        "{%0,%1,%2,%3}, {%4,%5,%6,%7}, {%8,%9}, {%0,%1,%2,%3};"
        : "+f"(d[0]), "+f"(d[1]), "+f"(d[2]), "+f"(d[3])
        : "r"(a[0]), "r"(a[1]), "r"(a[2]), "r"(a[3]), "r"(b0), "r"(b1));
}

__device__ __forceinline__ unsigned bf2u(__nv_bfloat162 v) {
    return *(unsigned*)&v;
}

// ---------------------------------------------------------------------------
// Vectorized bf16 hi/lo split
// ---------------------------------------------------------------------------
__global__ void split_bf16(const float4* __restrict__ src,
                           uint2* __restrict__ h, uint2* __restrict__ l, int n4)
{
    int i = blockIdx.x * blockDim.x + threadIdx.x;
    if (i >= n4) return;
    float4 v = src[i];
    __nv_bfloat162 h0 = __floats2bfloat162_rn(v.x, v.y);
    __nv_bfloat162 h1 = __floats2bfloat162_rn(v.z, v.w);
    __nv_bfloat162 l0 = __floats2bfloat162_rn(v.x - __bfloat162float(h0.x),
                                              v.y - __bfloat162float(h0.y));
    __nv_bfloat162 l1 = __floats2bfloat162_rn(v.z - __bfloat162float(h1.x),
                                              v.w - __bfloat162float(h1.y));
    h[i] = make_uint2(bf2u(h0), bf2u(h1));
    l[i] = make_uint2(bf2u(l0), bf2u(l1));
}

// ---------------------------------------------------------------------------
// bf16x3 GEMM, cp.async double-buffered:  C[M,N] = A[M,K] * B[N,K]^T
// ---------------------------------------------------------------------------
#define ROWU 20
#define ARRU (128 * ROWU)
#define STGU (4 * ARRU)

__global__ __launch_bounds__(256) void gemm_bf16x3_nt(
    const __nv_bfloat16* __restrict__ Agh, const __nv_bfloat16* __restrict__ Agl,
    const __nv_bfloat16* __restrict__ Bgh, const __nv_bfloat16* __restrict__ Bgl,
    float* __restrict__ C, int M, int N, int K)
{
    extern __shared__ unsigned sm[];

    int tid = threadIdx.x, wid = tid >> 5, lane = tid & 31;
    int wm = (wid & 3) * 32, wn = (wid >> 2) * 64;
    int bm = blockIdx.y * 128, bn = blockIdx.x * 128;
    int g = lane >> 2, tg = lane & 3;
    int lr = tid >> 2, lch = tid & 3;

    unsigned smem_base = (unsigned)__cvta_generic_to_shared(sm);

    float acc[2][8][4];
#pragma unroll
    for (int i = 0; i < 2; i++)
#pragma unroll
        for (int j = 0; j < 8; j++)
#pragma unroll
            for (int c = 0; c < 4; c++) acc[i][j][c] = 0.f;

    auto issue = [&](int s, int k0) {
#pragma unroll
        for (int p = 0; p < 2; p++) {
            int row = lr + p * 64;
            unsigned soff = smem_base + (unsigned)(s * STGU + row * ROWU + lch * 4) * 4;
            const __nv_bfloat16* ga = Agh + (size_t)(bm + row) * K + k0 + lch * 8;
            asm volatile("cp.async.cg.shared.global [%0], [%1], 16;"
                         :: "r"(soff), "l"(ga));
            ga = Agl + (size_t)(bm + row) * K + k0 + lch * 8;
            asm volatile("cp.async.cg.shared.global [%0], [%1], 16;"
                         :: "r"(soff + ARRU * 4), "l"(ga));
            const __nv_bfloat16* gb = Bgh + (size_t)(bn + row) * K + k0 + lch * 8;
            asm volatile("cp.async.cg.shared.global [%0], [%1], 16;"
                         :: "r"(soff + 2 * ARRU * 4), "l"(gb));
            gb = Bgl + (size_t)(bn + row) * K + k0 + lch * 8;
            asm volatile("cp.async.cg.shared.global [%0], [%1], 16;"
                         :: "r"(soff + 3 * ARRU * 4), "l"(gb));
        }
    };

    int nk = K / 32;
    issue(0, 0);
    asm volatile("cp.async.commit_group;");

    for (int it = 0; it < nk; it++) {
        if (it + 1 < nk) {
            issue((it + 1) & 1, (it + 1) * 32);
            asm volatile("cp.async.commit_group;");
            asm volatile("cp.async.wait_group 1;");
        } else {
            asm volatile("cp.async.wait_group 0;");
        }
        __syncthreads();

        const unsigned* Ah_s = sm + (it & 1) * STGU;
        const unsigned* Al_s = Ah_s + ARRU;
        const unsigned* Bh_s = Ah_s + 2 * ARRU;
        const unsigned* Bl_s = Ah_s + 3 * ARRU;

#pragma unroll
        for (int ks = 0; ks < 2; ks++) {
            unsigned ah[2][4], al[2][4];
#pragma unroll
            for (int tm = 0; tm < 2; tm++) {
                int i0 = (wm + tm * 16 + g) * ROWU + ks * 8 + tg;
                ah[tm][0] = Ah_s[i0];             ah[tm][1] = Ah_s[i0 + 8 * ROWU];
                ah[tm][2] = Ah_s[i0 + 4];         ah[tm][3] = Ah_s[i0 + 8 * ROWU + 4];
                al[tm][0] = Al_s[i0];             al[tm][1] = Al_s[i0 + 8 * ROWU];
                al[tm][2] = Al_s[i0 + 4];         al[tm][3] = Al_s[i0 + 8 * ROWU + 4];
            }
#pragma unroll
            for (int nt = 0; nt < 8; nt++) {
                int ib = (wn + nt * 8 + g) * ROWU + ks * 8 + tg;
                unsigned bh0 = Bh_s[ib], bh1 = Bh_s[ib + 4];
                unsigned bl0 = Bl_s[ib], bl1 = Bl_s[ib + 4];
#pragma unroll
                for (int tm = 0; tm < 2; tm++) {
                    mma_bf16(acc[tm][nt], ah[tm], bh0, bh1);
                    mma_bf16(acc[tm][nt], al[tm], bh0, bh1);
                    mma_bf16(acc[tm][nt], ah[tm], bl0, bl1);
                }
            }
        }
        __syncthreads();
    }

#pragma unroll
    for (int tm = 0; tm < 2; tm++)
#pragma unroll
        for (int nt = 0; nt < 8; nt++) {
            int row = bm + wm + tm * 16 + g;
            int col = bn + wn + nt * 8 + 2 * tg;
            *(float2*)(C + (size_t)row * N + col) =
                make_float2(acc[tm][nt][0], acc[tm][nt][1]);
            *(float2*)(C + (size_t)(row + 8) * N + col) =
                make_float2(acc[tm][nt][2], acc[tm][nt][3]);
        }
}

// ---------------------------------------------------------------------------
// RoPE + tf32 conversion into head-major attention operands.
// slots: 0..31 Q heads (rotate, scale), 32..39 K heads (rotate), 40..47 V (copy).
// ---------------------------------------------------------------------------
__global__ void rope_conv_kernel()
{
    int idx = blockIdx.x * blockDim.x + threadIdx.x;
    const int total = S * (NH + 2 * NKV) * 32;
    if (idx >= total) return;

    int i  = idx & 31;
    int r  = idx >> 5;
    int hs = r % (NH + 2 * NKV);
    int s  = r / (NH + 2 * NKV);

    if (hs < NH + NKV) {
        float inv_freq = __powf(10000.0f, -(float)i / 32.0f);
        float angle = (float)s * inv_freq;
        float c, sn;
        sincosf(angle, &sn, &c);

        if (hs < NH) {
            const float* base = g_q + (size_t)s * Hdim + hs * HD;
            float x1 = base[i], x2 = base[i + 32];
            unsigned* dst = g_qt + ((size_t)hs * S + s) * HD;
            dst[i]      = f2tf((x1 * c - x2 * sn) * SCALE);
            dst[i + 32] = f2tf((x2 * c + x1 * sn) * SCALE);
        } else {
            int kvh = hs - NH;
            const float* base = g_kv + (size_t)s * 1024 + kvh * HD;
            float x1 = base[i], x2 = base[i + 32];
            unsigned* dst = g_kt + ((size_t)kvh * S + s) * HD;
            dst[i]      = f2tf(x1 * c - x2 * sn);
            dst[i + 32] = f2tf(x2 * c + x1 * sn);
        }
    } else {
        int kvh = hs - NH - NKV;
        const float* base = g_kv + (size_t)s * 1024 + 512 + kvh * HD;
        unsigned* dst = g_vt + ((size_t)kvh * S + s) * HD;
        dst[i]      = f2tf(base[i]);
        dst[i + 32] = f2tf(base[i + 32]);
    }
}

// ---------------------------------------------------------------------------
// Tensor-core flash attention (causal), tf32, cp.async double-buffered K/V.
// grid (S/128, NH), 256 threads (8 warps x 16 q-rows = 128 rows/block).
// Smem: 2 x (K[64][68] + V[64][72])  +  QP[128][68] (Q staging, then P).
// ---------------------------------------------------------------------------
#define KSTR 68
#define VSTR 72
#define KBUF (64 * KSTR)            // 4352 u32
#define VBUF (64 * VSTR)            // 4608 u32
#define BUFU (KBUF + VBUF)          // 8960 u32
#define QPOFF (2 * BUFU)            // 17920 u32
#define ATTN_SMEM_B ((2 * BUFU + 128 * KSTR) * 4)   // 106496 B

__global__ __launch_bounds__(256) void flash_attn_tc()
{
    extern __shared__ unsigned sm[];

    int h   = blockIdx.y;
    int kvh = h >> 2;
    int q0  = ((int)gridDim.x - 1 - (int)blockIdx.x) * 128;  // heavy blocks first
    int tid = threadIdx.x;
    int w    = tid >> 5;
    int lane = tid & 31;
    int g    = lane >> 2;
    int tg   = lane & 3;

    unsigned smem_base = (unsigned)__cvta_generic_to_shared(sm);
    unsigned* QP = sm + QPOFF;

    // Stage Q (tf32, pre-scaled, contiguous head-major)
    {
        const unsigned* qsrc = g_qt + ((size_t)h * S + q0) * HD;
#pragma unroll
        for (int e2 = 0; e2 < 8; e2++) {
            int e = tid + e2 * 256;
            int rr = e >> 4, c = (e & 15) * 4;
            *(uint4*)(QP + rr * KSTR + c) = *(const uint4*)(qsrc + rr * 64 + c);
        }
    }
    __syncthreads();

    // Resident Q fragments
    unsigned qa[8][4];
#pragma unroll
    for (int kt = 0; kt < 8; kt++) {
        int base = (w * 16 + g) * KSTR + kt * 8 + tg;
        qa[kt][0] = QP[base];
        qa[kt][1] = QP[base + 8 * KSTR];
        qa[kt][2] = QP[base + 4];
        qa[kt][3] = QP[base + 8 * KSTR + 4];
    }

    const unsigned* kg = g_kt + (size_t)kvh * S * HD;
    const unsigned* vg = g_vt + (size_t)kvh * S * HD;

    auto stage = [&](int buf, int kk) {
        unsigned koff = smem_base + (unsigned)(buf * BUFU) * 4;
        unsigned voff = koff + KBUF * 4;
#pragma unroll
        for (int e2 = 0; e2 < 4; e2++) {
            int e = tid + e2 * 256;
            int rr = e >> 4, c = (e & 15) * 4;
            const unsigned* gk = kg + (size_t)(kk + rr) * HD + c;
            const unsigned* gv = vg + (size_t)(kk + rr) * HD + c;
            asm volatile("cp.async.cg.shared.global [%0], [%1], 16;"
                         :: "r"(koff + (unsigned)(rr * KSTR + c) * 4), "l"(gk));
            asm volatile("cp.async.cg.shared.global [%0], [%1], 16;"
                         :: "r"(voff + (unsigned)(rr * VSTR + c) * 4), "l"(gv));
        }
    };

    float oacc[8][4];
#pragma unroll
    for (int nt = 0; nt < 8; nt++)
#pragma unroll
        for (int c = 0; c < 4; c++) oacc[nt][c] = 0.f;

    float m0 = -1e30f, m1 = -1e30f, l0 = 0.f, l1 = 0.f;
    int row0 = q0 + w * 16 + g;
    int row1 = row0 + 8;
    unsigned* Pw = QP + w * 16 * KSTR;

    int nch = (q0 + 128) / 64;
    stage(0, 0);
    asm volatile("cp.async.commit_group;");

    for (int it = 0; it < nch; it++) {
        int kk = it * 64;
        if (it + 1 < nch) {
            stage((it + 1) & 1, kk + 64);
            asm volatile("cp.async.commit_group;");
            asm volatile("cp.async.wait_group 1;");
        } else {
            asm volatile("cp.async.wait_group 0;");
        }
        __syncthreads();

        const unsigned* Ks = sm + (it & 1) * BUFU;
        const unsigned* Vs = Ks + KBUF;

        // S = Q K^T
        float sacc[8][4];
#pragma unroll
        for (int nt = 0; nt < 8; nt++) {
#pragma unroll
            for (int c = 0; c < 4; c++) sacc[nt][c] = 0.f;
#pragma unroll
            for (int kt = 0; kt < 8; kt++) {
                int r = (nt * 8 + g) * KSTR + kt * 8 + tg;
                unsigned b[2] = { Ks[r], Ks[r + 4] };
                mma_tf32(sacc[nt], qa[kt], b);
            }
        }

        // Causal mask (chunk may straddle this warp's rows)
        if (kk + 63 > row0) {
#pragma unroll
            for (int nt = 0; nt < 8; nt++) {
                int col = kk + nt * 8 + 2 * tg;
                if (col     > row0) sacc[nt][0] = -1e30f;
                if (col + 1 > row0) sacc[nt][1] = -1e30f;
                if (col     > row1) sacc[nt][2] = -1e30f;
                if (col + 1 > row1) sacc[nt][3] = -1e30f;
            }
        }

        // Online softmax
        float mc0 = -1e30f, mc1 = -1e30f;
#pragma unroll
        for (int nt = 0; nt < 8; nt++) {
            mc0 = fmaxf(mc0, fmaxf(sacc[nt][0], sacc[nt][1]));
            mc1 = fmaxf(mc1, fmaxf(sacc[nt][2], sacc[nt][3]));
        }
        mc0 = fmaxf(mc0, __shfl_xor_sync(0xFFFFFFFFu, mc0, 1));
        mc0 = fmaxf(mc0, __shfl_xor_sync(0xFFFFFFFFu, mc0, 2));
        mc1 = fmaxf(mc1, __shfl_xor_sync(0xFFFFFFFFu, mc1, 1));
        mc1 = fmaxf(mc1, __shfl_xor_sync(0xFFFFFFFFu, mc1, 2));

        float mn0 = fmaxf(m0, mc0), mn1 = fmaxf(m1, mc1);
        float cr0 = __expf(m0 - mn0), cr1 = __expf(m1 - mn1);
        l0 *= cr0; l1 *= cr1;
#pragma unroll
        for (int nt = 0; nt < 8; nt++) {
            oacc[nt][0] *= cr0; oacc[nt][1] *= cr0;
            oacc[nt][2] *= cr1; oacc[nt][3] *= cr1;
        }
        m0 = mn0; m1 = mn1;

#pragma unroll
        for (int nt = 0; nt < 8; nt++) {
            float p0 = __expf(sacc[nt][0] - mn0);
            float p1 = __expf(sacc[nt][1] - mn0);
            float p2 = __expf(sacc[nt][2] - mn1);
            float p3 = __expf(sacc[nt][3] - mn1);
            l0 += p0 + p1;
            l1 += p2 + p3;
            int pb = g * KSTR + nt * 8 + 2 * tg;
            *(uint2*)(Pw + pb)            = make_uint2(f2tf(p0), f2tf(p1));
            *(uint2*)(Pw + pb + 8 * KSTR) = make_uint2(f2tf(p2), f2tf(p3));
        }
        __syncwarp();

        // O += P V
#pragma unroll
        for (int kt = 0; kt < 8; kt++) {
            unsigned pa[4];
            int pb = g * KSTR + kt * 8 + tg;
            pa[0] = Pw[pb];
            pa[1] = Pw[pb + 8 * KSTR];
            pa[2] = Pw[pb + 4];
            pa[3] = Pw[pb + 8 * KSTR + 4];
#pragma unroll
            for (int nt = 0; nt < 8; nt++) {
                int r = (kt * 8 + tg) * VSTR + nt * 8 + g;
                unsigned b[2] = { Vs[r], Vs[r + 4 * VSTR] };
                mma_tf32(oacc[nt], pa, b);
            }
        }
        __syncthreads();
    }

    l0 += __shfl_xor_sync(0xFFFFFFFFu, l0, 1);
    l0 += __shfl_xor_sync(0xFFFFFFFFu, l0, 2);
    l1 += __shfl_xor_sync(0xFFFFFFFFu, l1, 1);
    l1 += __shfl_xor_sync(0xFFFFFFFFu, l1, 2);
    float inv0 = 1.f / l0, inv1 = 1.f / l1;

    // Fused bf16 hi/lo split epilogue
#pragma unroll
    for (int nt = 0; nt < 8; nt++) {
        int col = h * HD + nt * 8 + 2 * tg;
        {
            float a0 = oacc[nt][0] * inv0, a1 = oacc[nt][1] * inv0;
            __nv_bfloat162 hv = __floats2bfloat162_rn(a0, a1);
            __nv_bfloat162 lv = __floats2bfloat162_rn(a0 - __bfloat162float(hv.x),
                                                      a1 - __bfloat162float(hv.y));
            *(__nv_bfloat162*)(s_at_h + (size_t)row0 * Hdim + col) = hv;
            *(__nv_bfloat162*)(s_at_l + (size_t)row0 * Hdim + col) = lv;
        }
        {
            float a0 = oacc[nt][2] * inv1, a1 = oacc[nt][3] * inv1;
            __nv_bfloat162 hv = __floats2bfloat162_rn(a0, a1);
            __nv_bfloat162 lv = __floats2bfloat162_rn(a0 - __bfloat162float(hv.x),
                                                      a1 - __bfloat162float(hv.y));
            *(__nv_bfloat162*)(s_at_h + (size_t)row1 * Hdim + col) = hv;
            *(__nv_bfloat162*)(s_at_l + (size_t)row1 * Hdim + col) = lv;
        }
    }
}

// ---------------------------------------------------------------------------
// Launch
// ---------------------------------------------------------------------------
extern "C" void kernel_launch(void* const* d_in, const int* in_sizes, int n_in,
                              void* d_out, int out_size)
{
    const float* hs = (const float*)d_in[0];
    const float* Wq = (const float*)d_in[1];
    const float* Wk = (const float*)d_in[2];
    const float* Wv = (const float*)d_in[3];
    const float* Wo = (const float*)d_in[4];
    float* out = (float*)d_out;

    float *qp, *kvp;
    __nv_bfloat16 *hsh, *hsl, *wqh, *wql, *wkvh, *wkvl, *woh, *wol, *ath, *atl;
    cudaGetSymbolAddress((void**)&qp,  g_q);
    cudaGetSymbolAddress((void**)&kvp, g_kv);
    cudaGetSymbolAddress((void**)&hsh, s_hs_h);  cudaGetSymbolAddress((void**)&hsl, s_hs_l);
    cudaGetSymbolAddress((void**)&wqh, s_wq_h);  cudaGetSymbolAddress((void**)&wql, s_wq_l);
    cudaGetSymbolAddress((void**)&wkvh, s_wkv_h); cudaGetSymbolAddress((void**)&wkvl, s_wkv_l);
    cudaGetSymbolAddress((void**)&woh, s_wo_h);  cudaGetSymbolAddress((void**)&wol, s_wo_l);
    cudaGetSymbolAddress((void**)&ath, s_at_h);  cudaGetSymbolAddress((void**)&atl, s_at_l);

    const int gemm_smem = 2 * STGU * 4;   // 81920 B
    cudaFuncSetAttribute(gemm_bf16x3_nt,
                         cudaFuncAttributeMaxDynamicSharedMemorySize, gemm_smem);
    cudaFuncSetAttribute(flash_attn_tc,
                         cudaFuncAttributeMaxDynamicSharedMemorySize, ATTN_SMEM_B);

    // Pre-split inputs to bf16 hi/lo
    const int ST = 256;
    auto splitN = [&](const float* src, __nv_bfloat16* h, __nv_bfloat16* l, int n) {
        int n4 = n / 4;
        split_bf16<<<(n4 + ST - 1) / ST, ST>>>((const float4*)src, (uint2*)h, (uint2*)l, n4);
    };
    splitN(hs, hsh, hsl, S * Hdim);
    splitN(Wq, wqh, wql, Hdim * Hdim);
    splitN(Wk, wkvh, wkvl, KVdim * Hdim);
    splitN(Wv, wkvh + (size_t)KVdim * Hdim, wkvl + (size_t)KVdim * Hdim, KVdim * Hdim);
    splitN(Wo, woh, wol, Hdim * Hdim);

    // Projections
    gemm_bf16x3_nt<<<dim3(Hdim / 128, S / 128), 256, gemm_smem>>>(
        hsh, hsl, wqh, wql, qp, S, Hdim, Hdim);
    gemm_bf16x3_nt<<<dim3(1024 / 128, S / 128), 256, gemm_smem>>>(
        hsh, hsl, wkvh, wkvl, kvp, S, 1024, Hdim);

    // RoPE + tf32 head-major conversion
    {
        int total = S * (NH + 2 * NKV) * 32;
        rope_conv_kernel<<<(total + 255) / 256, 256>>>();
    }

    // Attention (tf32 TC, cp.async pipelined; writes bf16 hi/lo directly)
    flash_attn_tc<<<dim3(S / 128, NH), 256, ATTN_SMEM_B>>>();

    // Output projection
    gemm_bf16x3_nt<<<dim3(Hdim / 128, S / 128), 256, gemm_smem>>>(
        ath, atl, woh, wol, out, S, Hdim, Hdim);
}

// round 7
// speedup vs baseline: 7.2889x; 1.0292x over previous
#include <cuda_runtime.h>
#include <cuda_bf16.h>
#include <math.h>

// Problem constants
#define S      2048
#define Hdim   2048
#define KVdim  512
#define NH     32
#define NKV    8
#define HD     64
#define SCALE  0.125f

// ---------------------------------------------------------------------------
// Scratch (device globals)
// ---------------------------------------------------------------------------
__device__ float g_q[S * Hdim];        // Q fp32 from GEMM
__device__ float g_kv[S * 1024];       // [s][0:512]=K, [s][512:1024]=V

// tf32 head-major operands for attention
__device__ unsigned g_qt[NH * S * HD];
__device__ unsigned g_kt[NKV * S * HD];
__device__ unsigned g_vt[NKV * S * HD];

// bf16 hi/lo pre-split operands for GEMMs
__device__ __nv_bfloat16 s_hs_h[S * Hdim],    s_hs_l[S * Hdim];
__device__ __nv_bfloat16 s_wq_h[Hdim * Hdim], s_wq_l[Hdim * Hdim];
__device__ __nv_bfloat16 s_wkv_h[1024 * Hdim], s_wkv_l[1024 * Hdim];
__device__ __nv_bfloat16 s_wo_h[Hdim * Hdim], s_wo_l[Hdim * Hdim];
__device__ __nv_bfloat16 s_at_h[S * Hdim],    s_at_l[S * Hdim];

__device__ __forceinline__ unsigned f2tf(float x) {
    unsigned r;
    asm("cvt.rna.tf32.f32 %0, %1;" : "=r"(r) : "f"(x));
    return r;
}

__device__ __forceinline__ void mma_tf32(float d[4], const unsigned a[4], const unsigned b[2]) {
    asm volatile(
        "mma.sync.aligned.m16n8k8.row.col.f32.tf32.tf32.f32 "
        "{%0,%1,%2,%3}, {%4,%5,%6,%7}, {%8,%9}, {%0,%1,%2,%3};"
        : "+f"(d[0]), "+f"(d[1]), "+f"(d[2]), "+f"(d[3])
        : "r"(a[0]), "r"(a[1]), "r"(a[2]), "r"(a[3]), "r"(b[0]), "r"(b[1]));
}

__device__ __forceinline__ void mma_bf16(float d[4], const unsigned a[4],
                                         unsigned b0, unsigned b1) {
    asm volatile(
        "mma.sync.aligned.m16n8k16.row.col.f32.bf16.bf16.f32 "
        "{%0,%1,%2,%3}, {%4,%5,%6,%7}, {%8,%9}, {%0,%1,%2,%3};"
        : "+f"(d[0]), "+f"(d[1]), "+f"(d[2]), "+f"(d[3])
        : "r"(a[0]), "r"(a[1]), "r"(a[2]), "r"(a[3]), "r"(b0), "r"(b1));
}

__device__ __forceinline__ unsigned bf2u(__nv_bfloat162 v) { return *(unsigned*)&v; }

// ---------------------------------------------------------------------------
// ONE fused bf16 hi/lo split over all 5 input tensors (float4 per thread).
// Layout (float4 units): hs | Wq | Wk | Wv | Wo
// ---------------------------------------------------------------------------
#define HS4  (S * Hdim / 4)        // 1048576
#define W4   (Hdim * Hdim / 4)     // 1048576
#define WK4  (KVdim * Hdim / 4)    // 262144
#define TOT4 (HS4 + W4 + 2 * WK4 + W4)

__device__ __forceinline__ void split_store(float4 v, uint2* h, uint2* l, int i)
{
    __nv_bfloat162 h0 = __floats2bfloat162_rn(v.x, v.y);
    __nv_bfloat162 h1 = __floats2bfloat162_rn(v.z, v.w);
    __nv_bfloat162 l0 = __floats2bfloat162_rn(v.x - __bfloat162float(h0.x),
                                              v.y - __bfloat162float(h0.y));
    __nv_bfloat162 l1 = __floats2bfloat162_rn(v.z - __bfloat162float(h1.x),
                                              v.w - __bfloat162float(h1.y));
    h[i] = make_uint2(bf2u(h0), bf2u(h1));
    l[i] = make_uint2(bf2u(l0), bf2u(l1));
}

__global__ __launch_bounds__(256) void split_all(
    const float4* __restrict__ hs, const float4* __restrict__ wq,
    const float4* __restrict__ wk, const float4* __restrict__ wv,
    const float4* __restrict__ wo)
{
    int i = blockIdx.x * blockDim.x + threadIdx.x;
    if (i >= TOT4) return;

    if (i < HS4) {
        split_store(hs[i], (uint2*)s_hs_h, (uint2*)s_hs_l, i);
    } else if (i < HS4 + W4) {
        int j = i - HS4;
        split_store(wq[j], (uint2*)s_wq_h, (uint2*)s_wq_l, j);
    } else if (i < HS4 + W4 + WK4) {
        int j = i - HS4 - W4;
        split_store(wk[j], (uint2*)s_wkv_h, (uint2*)s_wkv_l, j);
    } else if (i < HS4 + W4 + 2 * WK4) {
        int j = i - HS4 - W4 - WK4;
        split_store(wv[j], (uint2*)s_wkv_h + WK4, (uint2*)s_wkv_l + WK4, j);
    } else {
        int j = i - HS4 - W4 - 2 * WK4;
        split_store(wo[j], (uint2*)s_wo_h, (uint2*)s_wo_l, j);
    }
}

// ---------------------------------------------------------------------------
// bf16x3 GEMM, cp.async double-buffered:  C[M,N] = A[M,K] * B[N,K]^T
// 128x128 tile, BK=32, 256 threads.  launch_bounds(256,2) -> <=128 regs,
// 2 CTAs/SM (smem 80KB x2 = 160KB fits in 228KB).
// ---------------------------------------------------------------------------
#define ROWU 20
#define ARRU (128 * ROWU)
#define STGU (4 * ARRU)

__global__ __launch_bounds__(256, 2) void gemm_bf16x3_nt(
    const __nv_bfloat16* __restrict__ Agh, const __nv_bfloat16* __restrict__ Agl,
    const __nv_bfloat16* __restrict__ Bgh, const __nv_bfloat16* __restrict__ Bgl,
    float* __restrict__ C, int M, int N, int K)
{
    extern __shared__ unsigned sm[];

    int tid = threadIdx.x, wid = tid >> 5, lane = tid & 31;
    int wm = (wid & 3) * 32, wn = (wid >> 2) * 64;
    int bm = blockIdx.y * 128, bn = blockIdx.x * 128;
    int g = lane >> 2, tg = lane & 3;
    int lr = tid >> 2, lch = tid & 3;

    unsigned smem_base = (unsigned)__cvta_generic_to_shared(sm);

    float acc[2][8][4];
#pragma unroll
    for (int i = 0; i < 2; i++)
#pragma unroll
        for (int j = 0; j < 8; j++)
#pragma unroll
            for (int c = 0; c < 4; c++) acc[i][j][c] = 0.f;

    auto issue = [&](int s, int k0) {
#pragma unroll
        for (int p = 0; p < 2; p++) {
            int row = lr + p * 64;
            unsigned soff = smem_base + (unsigned)(s * STGU + row * ROWU + lch * 4) * 4;
            const __nv_bfloat16* ga = Agh + (size_t)(bm + row) * K + k0 + lch * 8;
            asm volatile("cp.async.cg.shared.global [%0], [%1], 16;"
                         :: "r"(soff), "l"(ga));
            ga = Agl + (size_t)(bm + row) * K + k0 + lch * 8;
            asm volatile("cp.async.cg.shared.global [%0], [%1], 16;"
                         :: "r"(soff + ARRU * 4), "l"(ga));
            const __nv_bfloat16* gb = Bgh + (size_t)(bn + row) * K + k0 + lch * 8;
            asm volatile("cp.async.cg.shared.global [%0], [%1], 16;"
                         :: "r"(soff + 2 * ARRU * 4), "l"(gb));
            gb = Bgl + (size_t)(bn + row) * K + k0 + lch * 8;
            asm volatile("cp.async.cg.shared.global [%0], [%1], 16;"
                         :: "r"(soff + 3 * ARRU * 4), "l"(gb));
        }
    };

    int nk = K / 32;
    issue(0, 0);
    asm volatile("cp.async.commit_group;");

    for (int it = 0; it < nk; it++) {
        if (it + 1 < nk) {
            issue((it + 1) & 1, (it + 1) * 32);
            asm volatile("cp.async.commit_group;");
            asm volatile("cp.async.wait_group 1;");
        } else {
            asm volatile("cp.async.wait_group 0;");
        }
        __syncthreads();

        const unsigned* Ah_s = sm + (it & 1) * STGU;
        const unsigned* Al_s = Ah_s + ARRU;
        const unsigned* Bh_s = Ah_s + 2 * ARRU;
        const unsigned* Bl_s = Ah_s + 3 * ARRU;

#pragma unroll
        for (int ks = 0; ks < 2; ks++) {
            unsigned ah[2][4], al[2][4];
#pragma unroll
            for (int tm = 0; tm < 2; tm++) {
                int i0 = (wm + tm * 16 + g) * ROWU + ks * 8 + tg;
                ah[tm][0] = Ah_s[i0];             ah[tm][1] = Ah_s[i0 + 8 * ROWU];
                ah[tm][2] = Ah_s[i0 + 4];         ah[tm][3] = Ah_s[i0 + 8 * ROWU + 4];
                al[tm][0] = Al_s[i0];             al[tm][1] = Al_s[i0 + 8 * ROWU];
                al[tm][2] = Al_s[i0 + 4];         al[tm][3] = Al_s[i0 + 8 * ROWU + 4];
            }
#pragma unroll
            for (int nt = 0; nt < 8; nt++) {
                int ib = (wn + nt * 8 + g) * ROWU + ks * 8 + tg;
                unsigned bh0 = Bh_s[ib], bh1 = Bh_s[ib + 4];
                unsigned bl0 = Bl_s[ib], bl1 = Bl_s[ib + 4];
#pragma unroll
                for (int tm = 0; tm < 2; tm++) {
                    mma_bf16(acc[tm][nt], ah[tm], bh0, bh1);
                    mma_bf16(acc[tm][nt], al[tm], bh0, bh1);
                    mma_bf16(acc[tm][nt], ah[tm], bl0, bl1);
                }
            }
        }
        __syncthreads();
    }

#pragma unroll
    for (int tm = 0; tm < 2; tm++)
#pragma unroll
        for (int nt = 0; nt < 8; nt++) {
            int row = bm + wm + tm * 16 + g;
            int col = bn + wn + nt * 8 + 2 * tg;
            *(float2*)(C + (size_t)row * N + col) =
                make_float2(acc[tm][nt][0], acc[tm][nt][1]);
            *(float2*)(C + (size_t)(row + 8) * N + col) =
                make_float2(acc[tm][nt][2], acc[tm][nt][3]);
        }
}

// ---------------------------------------------------------------------------
// RoPE + tf32 conversion into head-major attention operands.
// ---------------------------------------------------------------------------
__global__ void rope_conv_kernel()
{
    int idx = blockIdx.x * blockDim.x + threadIdx.x;
    const int total = S * (NH + 2 * NKV) * 32;
    if (idx >= total) return;

    int i  = idx & 31;
    int r  = idx >> 5;
    int hs = r % (NH + 2 * NKV);
    int s  = r / (NH + 2 * NKV);

    if (hs < NH + NKV) {
        float inv_freq = __powf(10000.0f, -(float)i / 32.0f);
        float angle = (float)s * inv_freq;
        float c, sn;
        sincosf(angle, &sn, &c);

        if (hs < NH) {
            const float* base = g_q + (size_t)s * Hdim + hs * HD;
            float x1 = base[i], x2 = base[i + 32];
            unsigned* dst = g_qt + ((size_t)hs * S + s) * HD;
            dst[i]      = f2tf((x1 * c - x2 * sn) * SCALE);
            dst[i + 32] = f2tf((x2 * c + x1 * sn) * SCALE);
        } else {
            int kvh = hs - NH;
            const float* base = g_kv + (size_t)s * 1024 + kvh * HD;
            float x1 = base[i], x2 = base[i + 32];
            unsigned* dst = g_kt + ((size_t)kvh * S + s) * HD;
            dst[i]      = f2tf(x1 * c - x2 * sn);
            dst[i + 32] = f2tf(x2 * c + x1 * sn);
        }
    } else {
        int kvh = hs - NH - NKV;
        const float* base = g_kv + (size_t)s * 1024 + 512 + kvh * HD;
        unsigned* dst = g_vt + ((size_t)kvh * S + s) * HD;
        dst[i]      = f2tf(base[i]);
        dst[i + 32] = f2tf(base[i + 32]);
    }
}

// ---------------------------------------------------------------------------
// Tensor-core flash attention (causal), tf32, cp.async double-buffered K/V.
// grid (S/128, NH), 256 threads (8 warps x 16 q-rows = 128 rows/block).
// ---------------------------------------------------------------------------
#define KSTR 68
#define VSTR 72
#define KBUF (64 * KSTR)
#define VBUF (64 * VSTR)
#define BUFU (KBUF + VBUF)
#define QPOFF (2 * BUFU)
#define ATTN_SMEM_B ((2 * BUFU + 128 * KSTR) * 4)

__global__ __launch_bounds__(256) void flash_attn_tc()
{
    extern __shared__ unsigned sm[];

    int h   = blockIdx.y;
    int kvh = h >> 2;
    int q0  = ((int)gridDim.x - 1 - (int)blockIdx.x) * 128;
    int tid = threadIdx.x;
    int w    = tid >> 5;
    int lane = tid & 31;
    int g    = lane >> 2;
    int tg   = lane & 3;

    unsigned smem_base = (unsigned)__cvta_generic_to_shared(sm);
    unsigned* QP = sm + QPOFF;

    {
        const unsigned* qsrc = g_qt + ((size_t)h * S + q0) * HD;
#pragma unroll
        for (int e2 = 0; e2 < 8; e2++) {
            int e = tid + e2 * 256;
            int rr = e >> 4, c = (e & 15) * 4;
            *(uint4*)(QP + rr * KSTR + c) = *(const uint4*)(qsrc + rr * 64 + c);
        }
    }
    __syncthreads();

    unsigned qa[8][4];
#pragma unroll
    for (int kt = 0; kt < 8; kt++) {
        int base = (w * 16 + g) * KSTR + kt * 8 + tg;
        qa[kt][0] = QP[base];
        qa[kt][1] = QP[base + 8 * KSTR];
        qa[kt][2] = QP[base + 4];
        qa[kt][3] = QP[base + 8 * KSTR + 4];
    }

    const unsigned* kg = g_kt + (size_t)kvh * S * HD;
    const unsigned* vg = g_vt + (size_t)kvh * S * HD;

    auto stage = [&](int buf, int kk) {
        unsigned koff = smem_base + (unsigned)(buf * BUFU) * 4;
        unsigned voff = koff + KBUF * 4;
#pragma unroll
        for (int e2 = 0; e2 < 4; e2++) {
            int e = tid + e2 * 256;
            int rr = e >> 4, c = (e & 15) * 4;
            const unsigned* gk = kg + (size_t)(kk + rr) * HD + c;
            const unsigned* gv = vg + (size_t)(kk + rr) * HD + c;
            asm volatile("cp.async.cg.shared.global [%0], [%1], 16;"
                         :: "r"(koff + (unsigned)(rr * KSTR + c) * 4), "l"(gk));
            asm volatile("cp.async.cg.shared.global [%0], [%1], 16;"
                         :: "r"(voff + (unsigned)(rr * VSTR + c) * 4), "l"(gv));
        }
    };

    float oacc[8][4];
#pragma unroll
    for (int nt = 0; nt < 8; nt++)
#pragma unroll
        for (int c = 0; c < 4; c++) oacc[nt][c] = 0.f;

    float m0 = -1e30f, m1 = -1e30f, l0 = 0.f, l1 = 0.f;
    int row0 = q0 + w * 16 + g;
    int row1 = row0 + 8;
    unsigned* Pw = QP + w * 16 * KSTR;

    int nch = (q0 + 128) / 64;
    stage(0, 0);
    asm volatile("cp.async.commit_group;");

    for (int it = 0; it < nch; it++) {
        int kk = it * 64;
        if (it + 1 < nch) {
            stage((it + 1) & 1, kk + 64);
            asm volatile("cp.async.commit_group;");
            asm volatile("cp.async.wait_group 1;");
        } else {
            asm volatile("cp.async.wait_group 0;");
        }
        __syncthreads();

        const unsigned* Ks = sm + (it & 1) * BUFU;
        const unsigned* Vs = Ks + KBUF;

        float sacc[8][4];
#pragma unroll
        for (int nt = 0; nt < 8; nt++) {
#pragma unroll
            for (int c = 0; c < 4; c++) sacc[nt][c] = 0.f;
#pragma unroll
            for (int kt = 0; kt < 8; kt++) {
                int r = (nt * 8 + g) * KSTR + kt * 8 + tg;
                unsigned b[2] = { Ks[r], Ks[r + 4] };
                mma_tf32(sacc[nt], qa[kt], b);
            }
        }

        if (kk + 63 > row0) {
#pragma unroll
            for (int nt = 0; nt < 8; nt++) {
                int col = kk + nt * 8 + 2 * tg;
                if (col     > row0) sacc[nt][0] = -1e30f;
                if (col + 1 > row0) sacc[nt][1] = -1e30f;
                if (col     > row1) sacc[nt][2] = -1e30f;
                if (col + 1 > row1) sacc[nt][3] = -1e30f;
            }
        }

        float mc0 = -1e30f, mc1 = -1e30f;
#pragma unroll
        for (int nt = 0; nt < 8; nt++) {
            mc0 = fmaxf(mc0, fmaxf(sacc[nt][0], sacc[nt][1]));
            mc1 = fmaxf(mc1, fmaxf(sacc[nt][2], sacc[nt][3]));
        }
        mc0 = fmaxf(mc0, __shfl_xor_sync(0xFFFFFFFFu, mc0, 1));
        mc0 = fmaxf(mc0, __shfl_xor_sync(0xFFFFFFFFu, mc0, 2));
        mc1 = fmaxf(mc1, __shfl_xor_sync(0xFFFFFFFFu, mc1, 1));
        mc1 = fmaxf(mc1, __shfl_xor_sync(0xFFFFFFFFu, mc1, 2));

        float mn0 = fmaxf(m0, mc0), mn1 = fmaxf(m1, mc1);
        float cr0 = __expf(m0 - mn0), cr1 = __expf(m1 - mn1);
        l0 *= cr0; l1 *= cr1;
#pragma unroll
        for (int nt = 0; nt < 8; nt++) {
            oacc[nt][0] *= cr0; oacc[nt][1] *= cr0;
            oacc[nt][2] *= cr1; oacc[nt][3] *= cr1;
        }
        m0 = mn0; m1 = mn1;

#pragma unroll
        for (int nt = 0; nt < 8; nt++) {
            float p0 = __expf(sacc[nt][0] - mn0);
            float p1 = __expf(sacc[nt][1] - mn0);
            float p2 = __expf(sacc[nt][2] - mn1);
            float p3 = __expf(sacc[nt][3] - mn1);
            l0 += p0 + p1;
            l1 += p2 + p3;
            int pb = g * KSTR + nt * 8 + 2 * tg;
            *(uint2*)(Pw + pb)            = make_uint2(f2tf(p0), f2tf(p1));
            *(uint2*)(Pw + pb + 8 * KSTR) = make_uint2(f2tf(p2), f2tf(p3));
        }
        __syncwarp();

#pragma unroll
        for (int kt = 0; kt < 8; kt++) {
            unsigned pa[4];
            int pb = g * KSTR + kt * 8 + tg;
            pa[0] = Pw[pb];
            pa[1] = Pw[pb + 8 * KSTR];
            pa[2] = Pw[pb + 4];
            pa[3] = Pw[pb + 8 * KSTR + 4];
#pragma unroll
            for (int nt = 0; nt < 8; nt++) {
                int r = (kt * 8 + tg) * VSTR + nt * 8 + g;
                unsigned b[2] = { Vs[r], Vs[r + 4 * VSTR] };
                mma_tf32(oacc[nt], pa, b);
            }
        }
        __syncthreads();
    }

    l0 += __shfl_xor_sync(0xFFFFFFFFu, l0, 1);
    l0 += __shfl_xor_sync(0xFFFFFFFFu, l0, 2);
    l1 += __shfl_xor_sync(0xFFFFFFFFu, l1, 1);
    l1 += __shfl_xor_sync(0xFFFFFFFFu, l1, 2);
    float inv0 = 1.f / l0, inv1 = 1.f / l1;

#pragma unroll
    for (int nt = 0; nt < 8; nt++) {
        int col = h * HD + nt * 8 + 2 * tg;
        {
            float a0 = oacc[nt][0] * inv0, a1 = oacc[nt][1] * inv0;
            __nv_bfloat162 hv = __floats2bfloat162_rn(a0, a1);
            __nv_bfloat162 lv = __floats2bfloat162_rn(a0 - __bfloat162float(hv.x),
                                                      a1 - __bfloat162float(hv.y));
            *(__nv_bfloat162*)(s_at_h + (size_t)row0 * Hdim + col) = hv;
            *(__nv_bfloat162*)(s_at_l + (size_t)row0 * Hdim + col) = lv;
        }
        {
            float a0 = oacc[nt][2] * inv1, a1 = oacc[nt][3] * inv1;
            __nv_bfloat162 hv = __floats2bfloat162_rn(a0, a1);
            __nv_bfloat162 lv = __floats2bfloat162_rn(a0 - __bfloat162float(hv.x),
                                                      a1 - __bfloat162float(hv.y));
            *(__nv_bfloat162*)(s_at_h + (size_t)row1 * Hdim + col) = hv;
            *(__nv_bfloat162*)(s_at_l + (size_t)row1 * Hdim + col) = lv;
        }
    }
}

// ---------------------------------------------------------------------------
// Launch
// ---------------------------------------------------------------------------
extern "C" void kernel_launch(void* const* d_in, const int* in_sizes, int n_in,
                              void* d_out, int out_size)
{
    const float* hs = (const float*)d_in[0];
    const float* Wq = (const float*)d_in[1];
    const float* Wk = (const float*)d_in[2];
    const float* Wv = (const float*)d_in[3];
    const float* Wo = (const float*)d_in[4];
    float* out = (float*)d_out;

    float *qp, *kvp;
    __nv_bfloat16 *hsh, *hsl, *wqh, *wql, *wkvh, *wkvl, *woh, *wol, *ath, *atl;
    cudaGetSymbolAddress((void**)&qp,  g_q);
    cudaGetSymbolAddress((void**)&kvp, g_kv);
    cudaGetSymbolAddress((void**)&hsh, s_hs_h);  cudaGetSymbolAddress((void**)&hsl, s_hs_l);
    cudaGetSymbolAddress((void**)&wqh, s_wq_h);  cudaGetSymbolAddress((void**)&wql, s_wq_l);
    cudaGetSymbolAddress((void**)&wkvh, s_wkv_h); cudaGetSymbolAddress((void**)&wkvl, s_wkv_l);
    cudaGetSymbolAddress((void**)&woh, s_wo_h);  cudaGetSymbolAddress((void**)&wol, s_wo_l);
    cudaGetSymbolAddress((void**)&ath, s_at_h);  cudaGetSymbolAddress((void**)&atl, s_at_l);

    const int gemm_smem = 2 * STGU * 4;   // 81920 B
    cudaFuncSetAttribute(gemm_bf16x3_nt,
                         cudaFuncAttributeMaxDynamicSharedMemorySize, gemm_smem);
    cudaFuncSetAttribute(flash_attn_tc,
                         cudaFuncAttributeMaxDynamicSharedMemorySize, ATTN_SMEM_B);

    // ONE fused split launch (keeps ncu skip-window clear of helper kernels)
    split_all<<<(TOT4 + 255) / 256, 256>>>(
        (const float4*)hs, (const float4*)Wq, (const float4*)Wk,
        (const float4*)Wv, (const float4*)Wo);

    // Projections
    gemm_bf16x3_nt<<<dim3(Hdim / 128, S / 128), 256, gemm_smem>>>(
        hsh, hsl, wqh, wql, qp, S, Hdim, Hdim);
    gemm_bf16x3_nt<<<dim3(1024 / 128, S / 128), 256, gemm_smem>>>(
        hsh, hsl, wkvh, wkvl, kvp, S, 1024, Hdim);

    // RoPE + tf32 head-major conversion
    {
        int total = S * (NH + 2 * NKV) * 32;
        rope_conv_kernel<<<(total + 255) / 256, 256>>>();
    }

    // Attention
    flash_attn_tc<<<dim3(S / 128, NH), 256, ATTN_SMEM_B>>>();

    // Output projection  (launch index 5 -> captured by ncu -s 5 -c 1)
    gemm_bf16x3_nt<<<dim3(Hdim / 128, S / 128), 256, gemm_smem>>>(
        ath, atl, woh, wol, out, S, Hdim, Hdim);
}

// round 8
// speedup vs baseline: 7.6970x; 1.0560x over previous
#include <cuda_runtime.h>
#include <cuda_bf16.h>
#include <math.h>

// Problem constants
#define S      2048
#define Hdim   2048
#define KVdim  512
#define NH     32
#define NKV    8
#define HD     64
#define SCALE  0.125f
#define NQKV   3072          // fused Q|K|V projection width

// ---------------------------------------------------------------------------
// Scratch (device globals)
// ---------------------------------------------------------------------------
__device__ float g_qkv[S * NQKV];      // [s][0:2048]=Q, [2048:2560]=K, [2560:3072]=V

// tf32 head-major operands for attention
__device__ unsigned g_qt[NH * S * HD];
__device__ unsigned g_kt[NKV * S * HD];
__device__ unsigned g_vt[NKV * S * HD];

// bf16 hi/lo pre-split operands for GEMMs
__device__ __nv_bfloat16 s_hs_h[S * Hdim],     s_hs_l[S * Hdim];
__device__ __nv_bfloat16 s_wa_h[NQKV * Hdim],  s_wa_l[NQKV * Hdim];  // Wq|Wk|Wv
__device__ __nv_bfloat16 s_wo_h[Hdim * Hdim],  s_wo_l[Hdim * Hdim];
__device__ __nv_bfloat16 s_at_h[S * Hdim],     s_at_l[S * Hdim];

__device__ __forceinline__ unsigned f2tf(float x) {
    unsigned r;
    asm("cvt.rna.tf32.f32 %0, %1;" : "=r"(r) : "f"(x));
    return r;
}

__device__ __forceinline__ void mma_tf32(float d[4], const unsigned a[4], const unsigned b[2]) {
    asm volatile(
        "mma.sync.aligned.m16n8k8.row.col.f32.tf32.tf32.f32 "
        "{%0,%1,%2,%3}, {%4,%5,%6,%7}, {%8,%9}, {%0,%1,%2,%3};"
        : "+f"(d[0]), "+f"(d[1]), "+f"(d[2]), "+f"(d[3])
        : "r"(a[0]), "r"(a[1]), "r"(a[2]), "r"(a[3]), "r"(b[0]), "r"(b[1]));
}

__device__ __forceinline__ void mma_bf16(float d[4], const unsigned a[4],
                                         unsigned b0, unsigned b1) {
    asm volatile(
        "mma.sync.aligned.m16n8k16.row.col.f32.bf16.bf16.f32 "
        "{%0,%1,%2,%3}, {%4,%5,%6,%7}, {%8,%9}, {%0,%1,%2,%3};"
        : "+f"(d[0]), "+f"(d[1]), "+f"(d[2]), "+f"(d[3])
        : "r"(a[0]), "r"(a[1]), "r"(a[2]), "r"(a[3]), "r"(b0), "r"(b1));
}

#define LDSM4(r, a)                                                          \
    asm volatile("ldmatrix.sync.aligned.m8n8.x4.shared.b16 {%0,%1,%2,%3}, [%4];" \
        : "=r"((r)[0]), "=r"((r)[1]), "=r"((r)[2]), "=r"((r)[3]) : "r"(a))

__device__ __forceinline__ unsigned bf2u(__nv_bfloat162 v) { return *(unsigned*)&v; }

// ---------------------------------------------------------------------------
// ONE fused bf16 hi/lo split over all 5 input tensors (float4 per thread).
// ---------------------------------------------------------------------------
#define HS4  (S * Hdim / 4)
#define W4   (Hdim * Hdim / 4)
#define WK4  (KVdim * Hdim / 4)
#define TOT4 (HS4 + W4 + 2 * WK4 + W4)

__device__ __forceinline__ void split_store(float4 v, uint2* h, uint2* l, int i)
{
    __nv_bfloat162 h0 = __floats2bfloat162_rn(v.x, v.y);
    __nv_bfloat162 h1 = __floats2bfloat162_rn(v.z, v.w);
    __nv_bfloat162 l0 = __floats2bfloat162_rn(v.x - __bfloat162float(h0.x),
                                              v.y - __bfloat162float(h0.y));
    __nv_bfloat162 l1 = __floats2bfloat162_rn(v.z - __bfloat162float(h1.x),
                                              v.w - __bfloat162float(h1.y));
    h[i] = make_uint2(bf2u(h0), bf2u(h1));
    l[i] = make_uint2(bf2u(l0), bf2u(l1));
}

__global__ __launch_bounds__(256) void split_all(
    const float4* __restrict__ hs, const float4* __restrict__ wq,
    const float4* __restrict__ wk, const float4* __restrict__ wv,
    const float4* __restrict__ wo)
{
    int i = blockIdx.x * blockDim.x + threadIdx.x;
    if (i >= TOT4) return;

    if (i < HS4) {
        split_store(hs[i], (uint2*)s_hs_h, (uint2*)s_hs_l, i);
    } else if (i < HS4 + W4) {
        int j = i - HS4;
        split_store(wq[j], (uint2*)s_wa_h, (uint2*)s_wa_l, j);
    } else if (i < HS4 + W4 + WK4) {
        int j = i - HS4 - W4;
        split_store(wk[j], (uint2*)s_wa_h + W4, (uint2*)s_wa_l + W4, j);
    } else if (i < HS4 + W4 + 2 * WK4) {
        int j = i - HS4 - W4 - WK4;
        split_store(wv[j], (uint2*)s_wa_h + W4 + WK4, (uint2*)s_wa_l + W4 + WK4, j);
    } else {
        int j = i - HS4 - W4 - 2 * WK4;
        split_store(wo[j], (uint2*)s_wo_h, (uint2*)s_wo_l, j);
    }
}

// ---------------------------------------------------------------------------
// bf16x3 GEMM, cp.async double-buffered, ldmatrix fragment loads.
// C[M,N] = A[M,K] * B[N,K]^T.  128x128 tile, BK=32, 256 threads.
// Row stride 20 u32: LDSM 8-row phases hit banks {20r%32} -> conflict-free.
// ---------------------------------------------------------------------------
#define ROWU 20
#define ARRU (128 * ROWU)
#define STGU (4 * ARRU)

__global__ __launch_bounds__(256, 2) void gemm_bf16x3_nt(
    const __nv_bfloat16* __restrict__ Agh, const __nv_bfloat16* __restrict__ Agl,
    const __nv_bfloat16* __restrict__ Bgh, const __nv_bfloat16* __restrict__ Bgl,
    float* __restrict__ C, int M, int N, int K)
{
    extern __shared__ unsigned sm[];

    int tid = threadIdx.x, wid = tid >> 5, lane = tid & 31;
    int wm = (wid & 3) * 32, wn = (wid >> 2) * 64;
    int bm = blockIdx.y * 128, bn = blockIdx.x * 128;
    int g = lane >> 2, tg = lane & 3;
    int lr = tid >> 2, lch = tid & 3;

    unsigned smem_base = (unsigned)__cvta_generic_to_shared(sm);

    // ldmatrix per-lane address components (in bytes, relative to array base)
    // A map: row = wm+tm*16+(lane&15), col byte = ks*32 + (lane>>4)*16
    unsigned a_row = (unsigned)(wm + (lane & 15)) * ROWU * 4 + (lane >> 4) * 16;
    // B map: row = wn+ntp*16+(lane&7)+((lane>>4)&1)*8, col byte = ks*32+((lane>>3)&1)*16
    unsigned b_row = (unsigned)(wn + (lane & 7) + ((lane >> 4) & 1) * 8) * ROWU * 4
                   + ((lane >> 3) & 1) * 16;

    float acc[2][8][4];
#pragma unroll
    for (int i = 0; i < 2; i++)
#pragma unroll
        for (int j = 0; j < 8; j++)
#pragma unroll
            for (int c = 0; c < 4; c++) acc[i][j][c] = 0.f;

    auto issue = [&](int s, int k0) {
#pragma unroll
        for (int p = 0; p < 2; p++) {
            int row = lr + p * 64;
            unsigned soff = smem_base + (unsigned)(s * STGU + row * ROWU + lch * 4) * 4;
            const __nv_bfloat16* ga = Agh + (size_t)(bm + row) * K + k0 + lch * 8;
            asm volatile("cp.async.cg.shared.global [%0], [%1], 16;"
                         :: "r"(soff), "l"(ga));
            ga = Agl + (size_t)(bm + row) * K + k0 + lch * 8;
            asm volatile("cp.async.cg.shared.global [%0], [%1], 16;"
                         :: "r"(soff + ARRU * 4), "l"(ga));
            const __nv_bfloat16* gb = Bgh + (size_t)(bn + row) * K + k0 + lch * 8;
            asm volatile("cp.async.cg.shared.global [%0], [%1], 16;"
                         :: "r"(soff + 2 * ARRU * 4), "l"(gb));
            gb = Bgl + (size_t)(bn + row) * K + k0 + lch * 8;
            asm volatile("cp.async.cg.shared.global [%0], [%1], 16;"
                         :: "r"(soff + 3 * ARRU * 4), "l"(gb));
        }
    };

    int nk = K / 32;
    issue(0, 0);
    asm volatile("cp.async.commit_group;");

    for (int it = 0; it < nk; it++) {
        if (it + 1 < nk) {
            issue((it + 1) & 1, (it + 1) * 32);
            asm volatile("cp.async.commit_group;");
            asm volatile("cp.async.wait_group 1;");
        } else {
            asm volatile("cp.async.wait_group 0;");
        }
        __syncthreads();

        unsigned buf = smem_base + (unsigned)((it & 1) * STGU) * 4;

#pragma unroll
        for (int ks = 0; ks < 2; ks++) {
            unsigned ah[2][4], al[2][4];
#pragma unroll
            for (int tm = 0; tm < 2; tm++) {
                unsigned aaddr = buf + a_row + (unsigned)(tm * 16 * ROWU * 4) + ks * 32;
                LDSM4(ah[tm], aaddr);
                LDSM4(al[tm], aaddr + ARRU * 4);
            }
#pragma unroll
            for (int ntp = 0; ntp < 4; ntp++) {
                unsigned bh[4], bl[4];
                unsigned baddr = buf + 2u * ARRU * 4 + b_row
                               + (unsigned)(ntp * 16 * ROWU * 4) + ks * 32;
                LDSM4(bh, baddr);
                LDSM4(bl, baddr + ARRU * 4);
#pragma unroll
                for (int tm = 0; tm < 2; tm++) {
                    mma_bf16(acc[tm][2 * ntp],     ah[tm], bh[0], bh[1]);
                    mma_bf16(acc[tm][2 * ntp],     al[tm], bh[0], bh[1]);
                    mma_bf16(acc[tm][2 * ntp],     ah[tm], bl[0], bl[1]);
                    mma_bf16(acc[tm][2 * ntp + 1], ah[tm], bh[2], bh[3]);
                    mma_bf16(acc[tm][2 * ntp + 1], al[tm], bh[2], bh[3]);
                    mma_bf16(acc[tm][2 * ntp + 1], ah[tm], bl[2], bl[3]);
                }
            }
        }
        __syncthreads();
    }

#pragma unroll
    for (int tm = 0; tm < 2; tm++)
#pragma unroll
        for (int nt = 0; nt < 8; nt++) {
            int row = bm + wm + tm * 16 + g;
            int col = bn + wn + nt * 8 + 2 * tg;
            *(float2*)(C + (size_t)row * N + col) =
                make_float2(acc[tm][nt][0], acc[tm][nt][1]);
            *(float2*)(C + (size_t)(row + 8) * N + col) =
                make_float2(acc[tm][nt][2], acc[tm][nt][3]);
        }
}

// ---------------------------------------------------------------------------
// RoPE + tf32 conversion into head-major attention operands (from g_qkv).
// ---------------------------------------------------------------------------
__global__ void rope_conv_kernel()
{
    int idx = blockIdx.x * blockDim.x + threadIdx.x;
    const int total = S * (NH + 2 * NKV) * 32;
    if (idx >= total) return;

    int i  = idx & 31;
    int r  = idx >> 5;
    int hs = r % (NH + 2 * NKV);
    int s  = r / (NH + 2 * NKV);

    if (hs < NH + NKV) {
        float inv_freq = __powf(10000.0f, -(float)i / 32.0f);
        float angle = (float)s * inv_freq;
        float c, sn;
        sincosf(angle, &sn, &c);

        if (hs < NH) {
            const float* base = g_qkv + (size_t)s * NQKV + hs * HD;
            float x1 = base[i], x2 = base[i + 32];
            unsigned* dst = g_qt + ((size_t)hs * S + s) * HD;
            dst[i]      = f2tf((x1 * c - x2 * sn) * SCALE);
            dst[i + 32] = f2tf((x2 * c + x1 * sn) * SCALE);
        } else {
            int kvh = hs - NH;
            const float* base = g_qkv + (size_t)s * NQKV + 2048 + kvh * HD;
            float x1 = base[i], x2 = base[i + 32];
            unsigned* dst = g_kt + ((size_t)kvh * S + s) * HD;
            dst[i]      = f2tf(x1 * c - x2 * sn);
            dst[i + 32] = f2tf(x2 * c + x1 * sn);
        }
    } else {
        int kvh = hs - NH - NKV;
        const float* base = g_qkv + (size_t)s * NQKV + 2560 + kvh * HD;
        unsigned* dst = g_vt + ((size_t)kvh * S + s) * HD;
        dst[i]      = f2tf(base[i]);
        dst[i + 32] = f2tf(base[i + 32]);
    }
}

// ---------------------------------------------------------------------------
// Tensor-core flash attention (unchanged from R7-passing version)
// ---------------------------------------------------------------------------
#define KSTR 68
#define VSTR 72
#define KBUF (64 * KSTR)
#define VBUF (64 * VSTR)
#define BUFU (KBUF + VBUF)
#define QPOFF (2 * BUFU)
#define ATTN_SMEM_B ((2 * BUFU + 128 * KSTR) * 4)

__global__ __launch_bounds__(256) void flash_attn_tc()
{
    extern __shared__ unsigned sm[];

    int h   = blockIdx.y;
    int kvh = h >> 2;
    int q0  = ((int)gridDim.x - 1 - (int)blockIdx.x) * 128;
    int tid = threadIdx.x;
    int w    = tid >> 5;
    int lane = tid & 31;
    int g    = lane >> 2;
    int tg   = lane & 3;

    unsigned smem_base = (unsigned)__cvta_generic_to_shared(sm);
    unsigned* QP = sm + QPOFF;

    {
        const unsigned* qsrc = g_qt + ((size_t)h * S + q0) * HD;
#pragma unroll
        for (int e2 = 0; e2 < 8; e2++) {
            int e = tid + e2 * 256;
            int rr = e >> 4, c = (e & 15) * 4;
            *(uint4*)(QP + rr * KSTR + c) = *(const uint4*)(qsrc + rr * 64 + c);
        }
    }
    __syncthreads();

    unsigned qa[8][4];
#pragma unroll
    for (int kt = 0; kt < 8; kt++) {
        int base = (w * 16 + g) * KSTR + kt * 8 + tg;
        qa[kt][0] = QP[base];
        qa[kt][1] = QP[base + 8 * KSTR];
        qa[kt][2] = QP[base + 4];
        qa[kt][3] = QP[base + 8 * KSTR + 4];
    }

    const unsigned* kg = g_kt + (size_t)kvh * S * HD;
    const unsigned* vg = g_vt + (size_t)kvh * S * HD;

    auto stage = [&](int buf, int kk) {
        unsigned koff = smem_base + (unsigned)(buf * BUFU) * 4;
        unsigned voff = koff + KBUF * 4;
#pragma unroll
        for (int e2 = 0; e2 < 4; e2++) {
            int e = tid + e2 * 256;
            int rr = e >> 4, c = (e & 15) * 4;
            const unsigned* gk = kg + (size_t)(kk + rr) * HD + c;
            const unsigned* gv = vg + (size_t)(kk + rr) * HD + c;
            asm volatile("cp.async.cg.shared.global [%0], [%1], 16;"
                         :: "r"(koff + (unsigned)(rr * KSTR + c) * 4), "l"(gk));
            asm volatile("cp.async.cg.shared.global [%0], [%1], 16;"
                         :: "r"(voff + (unsigned)(rr * VSTR + c) * 4), "l"(gv));
        }
    };

    float oacc[8][4];
#pragma unroll
    for (int nt = 0; nt < 8; nt++)
#pragma unroll
        for (int c = 0; c < 4; c++) oacc[nt][c] = 0.f;

    float m0 = -1e30f, m1 = -1e30f, l0 = 0.f, l1 = 0.f;
    int row0 = q0 + w * 16 + g;
    int row1 = row0 + 8;
    unsigned* Pw = QP + w * 16 * KSTR;

    int nch = (q0 + 128) / 64;
    stage(0, 0);
    asm volatile("cp.async.commit_group;");

    for (int it = 0; it < nch; it++) {
        int kk = it * 64;
        if (it + 1 < nch) {
            stage((it + 1) & 1, kk + 64);
            asm volatile("cp.async.commit_group;");
            asm volatile("cp.async.wait_group 1;");
        } else {
            asm volatile("cp.async.wait_group 0;");
        }
        __syncthreads();

        const unsigned* Ks = sm + (it & 1) * BUFU;
        const unsigned* Vs = Ks + KBUF;

        float sacc[8][4];
#pragma unroll
        for (int nt = 0; nt < 8; nt++) {
#pragma unroll
            for (int c = 0; c < 4; c++) sacc[nt][c] = 0.f;
#pragma unroll
            for (int kt = 0; kt < 8; kt++) {
                int r = (nt * 8 + g) * KSTR + kt * 8 + tg;
                unsigned b[2] = { Ks[r], Ks[r + 4] };
                mma_tf32(sacc[nt], qa[kt], b);
            }
        }

        if (kk + 63 > row0) {
#pragma unroll
            for (int nt = 0; nt < 8; nt++) {
                int col = kk + nt * 8 + 2 * tg;
                if (col     > row0) sacc[nt][0] = -1e30f;
                if (col + 1 > row0) sacc[nt][1] = -1e30f;
                if (col     > row1) sacc[nt][2] = -1e30f;
                if (col + 1 > row1) sacc[nt][3] = -1e30f;
            }
        }

        float mc0 = -1e30f, mc1 = -1e30f;
#pragma unroll
        for (int nt = 0; nt < 8; nt++) {
            mc0 = fmaxf(mc0, fmaxf(sacc[nt][0], sacc[nt][1]));
            mc1 = fmaxf(mc1, fmaxf(sacc[nt][2], sacc[nt][3]));
        }
        mc0 = fmaxf(mc0, __shfl_xor_sync(0xFFFFFFFFu, mc0, 1));
        mc0 = fmaxf(mc0, __shfl_xor_sync(0xFFFFFFFFu, mc0, 2));
        mc1 = fmaxf(mc1, __shfl_xor_sync(0xFFFFFFFFu, mc1, 1));
        mc1 = fmaxf(mc1, __shfl_xor_sync(0xFFFFFFFFu, mc1, 2));

        float mn0 = fmaxf(m0, mc0), mn1 = fmaxf(m1, mc1);
        float cr0 = __expf(m0 - mn0), cr1 = __expf(m1 - mn1);
        l0 *= cr0; l1 *= cr1;
#pragma unroll
        for (int nt = 0; nt < 8; nt++) {
            oacc[nt][0] *= cr0; oacc[nt][1] *= cr0;
            oacc[nt][2] *= cr1; oacc[nt][3] *= cr1;
        }
        m0 = mn0; m1 = mn1;

#pragma unroll
        for (int nt = 0; nt < 8; nt++) {
            float p0 = __expf(sacc[nt][0] - mn0);
            float p1 = __expf(sacc[nt][1] - mn0);
            float p2 = __expf(sacc[nt][2] - mn1);
            float p3 = __expf(sacc[nt][3] - mn1);
            l0 += p0 + p1;
            l1 += p2 + p3;
            int pb = g * KSTR + nt * 8 + 2 * tg;
            *(uint2*)(Pw + pb)            = make_uint2(f2tf(p0), f2tf(p1));
            *(uint2*)(Pw + pb + 8 * KSTR) = make_uint2(f2tf(p2), f2tf(p3));
        }
        __syncwarp();

#pragma unroll
        for (int kt = 0; kt < 8; kt++) {
            unsigned pa[4];
            int pb = g * KSTR + kt * 8 + tg;
            pa[0] = Pw[pb];
            pa[1] = Pw[pb + 8 * KSTR];
            pa[2] = Pw[pb + 4];
            pa[3] = Pw[pb + 8 * KSTR + 4];
#pragma unroll
            for (int nt = 0; nt < 8; nt++) {
                int r = (kt * 8 + tg) * VSTR + nt * 8 + g;
                unsigned b[2] = { Vs[r], Vs[r + 4 * VSTR] };
                mma_tf32(oacc[nt], pa, b);
            }
        }
        __syncthreads();
    }

    l0 += __shfl_xor_sync(0xFFFFFFFFu, l0, 1);
    l0 += __shfl_xor_sync(0xFFFFFFFFu, l0, 2);
    l1 += __shfl_xor_sync(0xFFFFFFFFu, l1, 1);
    l1 += __shfl_xor_sync(0xFFFFFFFFu, l1, 2);
    float inv0 = 1.f / l0, inv1 = 1.f / l1;

#pragma unroll
    for (int nt = 0; nt < 8; nt++) {
        int col = h * HD + nt * 8 + 2 * tg;
        {
            float a0 = oacc[nt][0] * inv0, a1 = oacc[nt][1] * inv0;
            __nv_bfloat162 hv = __floats2bfloat162_rn(a0, a1);
            __nv_bfloat162 lv = __floats2bfloat162_rn(a0 - __bfloat162float(hv.x),
                                                      a1 - __bfloat162float(hv.y));
            *(__nv_bfloat162*)(s_at_h + (size_t)row0 * Hdim + col) = hv;
            *(__nv_bfloat162*)(s_at_l + (size_t)row0 * Hdim + col) = lv;
        }
        {
            float a0 = oacc[nt][2] * inv1, a1 = oacc[nt][3] * inv1;
            __nv_bfloat162 hv = __floats2bfloat162_rn(a0, a1);
            __nv_bfloat162 lv = __floats2bfloat162_rn(a0 - __bfloat162float(hv.x),
                                                      a1 - __bfloat162float(hv.y));
            *(__nv_bfloat162*)(s_at_h + (size_t)row1 * Hdim + col) = hv;
            *(__nv_bfloat162*)(s_at_l + (size_t)row1 * Hdim + col) = lv;
        }
    }
}

// ---------------------------------------------------------------------------
// Launch
// ---------------------------------------------------------------------------
extern "C" void kernel_launch(void* const* d_in, const int* in_sizes, int n_in,
                              void* d_out, int out_size)
{
    const float* hs = (const float*)d_in[0];
    const float* Wq = (const float*)d_in[1];
    const float* Wk = (const float*)d_in[2];
    const float* Wv = (const float*)d_in[3];
    const float* Wo = (const float*)d_in[4];
    float* out = (float*)d_out;

    float* qkvp;
    __nv_bfloat16 *hsh, *hsl, *wah, *wal, *woh, *wol, *ath, *atl;
    cudaGetSymbolAddress((void**)&qkvp, g_qkv);
    cudaGetSymbolAddress((void**)&hsh, s_hs_h);  cudaGetSymbolAddress((void**)&hsl, s_hs_l);
    cudaGetSymbolAddress((void**)&wah, s_wa_h);  cudaGetSymbolAddress((void**)&wal, s_wa_l);
    cudaGetSymbolAddress((void**)&woh, s_wo_h);  cudaGetSymbolAddress((void**)&wol, s_wo_l);
    cudaGetSymbolAddress((void**)&ath, s_at_h);  cudaGetSymbolAddress((void**)&atl, s_at_l);

    const int gemm_smem = 2 * STGU * 4;   // 81920 B
    cudaFuncSetAttribute(gemm_bf16x3_nt,
                         cudaFuncAttributeMaxDynamicSharedMemorySize, gemm_smem);
    cudaFuncSetAttribute(flash_attn_tc,
                         cudaFuncAttributeMaxDynamicSharedMemorySize, ATTN_SMEM_B);

    // ONE fused split launch
    split_all<<<(TOT4 + 255) / 256, 256>>>(
        (const float4*)hs, (const float4*)Wq, (const float4*)Wk,
        (const float4*)Wv, (const float4*)Wo);

    // Fused QKV projection (N=3072)
    gemm_bf16x3_nt<<<dim3(NQKV / 128, S / 128), 256, gemm_smem>>>(
        hsh, hsl, wah, wal, qkvp, S, NQKV, Hdim);

    // RoPE + tf32 head-major conversion
    {
        int total = S * (NH + 2 * NKV) * 32;
        rope_conv_kernel<<<(total + 255) / 256, 256>>>();
    }

    // Attention
    flash_attn_tc<<<dim3(S / 128, NH), 256, ATTN_SMEM_B>>>();

    // Output projection
    gemm_bf16x3_nt<<<dim3(Hdim / 128, S / 128), 256, gemm_smem>>>(
        ath, atl, woh, wol, out, S, Hdim, Hdim);
}